// round 10
// baseline (speedup 1.0000x reference)
#include <cuda_runtime.h>
#include <cuda.h>
#include <cstdint>

// ----------------------------------------------------------------------------
// BasePatchOrthogonalMix as one GEMM: out[m,e] = sum_d patch[m,d] * W[e,d]
//   m = (b,hp,wp) = 65536,  d/e = (c,ph,pw) = 1024
//
// R8:
//  1) pre_x (R7, kept): rna-round + patch-transpose x -> g_Xr, XOR smem swizzle.
//  2) pre_w: rna-round W -> g_Wr.
//  3) patch_mix_tc: cta_group::2 tcgen05 tf32 GEMM. 2-CTA pair computes a
//     512x256 tile (two M=256 atoms, N=256); per CTA per K-iter operands are
//     48 KB (A 256 rows + B 128-row N-half) vs 64 KB for cg1 256x256 -> LTS
//     bytes x0.75 (the measured bottleneck: R6 GEMM sat exactly on the
//     ~6300 B/cyc LTS cap). Cluster 2 packs 148 SMs perfectly, no stranding.
//     TMA completes on the leader's full barrier (cta_group::2 TMA, bit-24
//     mask); leader-issued MMAs; stages freed via multicast cg2 commit.
//  Fallback warp-mma kernel + numRegs dispatch retained.
// ----------------------------------------------------------------------------

#if defined(__CUDA_ARCH__) && (defined(__CUDA_ARCH_FEAT_SM103_ALL) || defined(__CUDA_ARCH_FEAT_SM100_ALL))
#define TCGEN05_OK 1
#else
#define TCGEN05_OK 0
#endif

__device__ float g_Xr[65536ull * 1024];
__device__ float g_Wr[1024 * 1024];

// ======================== common helpers ====================================

__device__ __forceinline__ uint32_t f2tf32(float f) {
    uint32_t u;
    asm("cvt.rna.tf32.f32 %0, %1;" : "=r"(u) : "f"(f));
    return u;
}

__device__ __forceinline__ float4 cvt4(float4 v) {
    float4 t;
    t.x = __uint_as_float(f2tf32(v.x));
    t.y = __uint_as_float(f2tf32(v.y));
    t.z = __uint_as_float(f2tf32(v.z));
    t.w = __uint_as_float(f2tf32(v.w));
    return t;
}

__device__ __forceinline__ uint32_t smem_u32(const void* p) {
    uint32_t a;
    asm("{ .reg .u64 t; cvta.to.shared.u64 t, %1; cvt.u32.u64 %0, t; }" : "=r"(a) : "l"(p));
    return a;
}

// ======================== pre-pass kernels ==================================

// pre_x: CTA = (b, hp, cb): 16 channels x 4 ph x 256 w -> 64 m-rows x 256 d.
// smem tile: 64 rows x 64 float4, XOR-swizzled col4' = col4 ^ (row & 7).
__global__ void __launch_bounds__(256) pre_x(const float* __restrict__ x) {
    extern __shared__ float4 sm[];   // 64 * 64 float4 = 64 KB
    const int t  = threadIdx.x;
    const int cb = blockIdx.x & 3;
    const int hp = (blockIdx.x >> 2) & 63;
    const int b  = blockIdx.x >> 8;

    {   // load: row r = c'*4+ph; 256 floats of x[b][cb*16+c'][hp*4+ph][:]
        const int r = t >> 2, i = t & 3;
        const int c  = cb * 16 + (r >> 2);
        const int ph = r & 3;
        const float4* src = (const float4*)(x + (((size_t)(b * 64 + c)) << 16)
                                              + ((hp * 4 + ph) << 8));
#pragma unroll
        for (int j = 0; j < 16; ++j) {
            int f = j * 4 + i;
            sm[r * 64 + (f ^ (r & 7))] = src[f];
        }
    }
    __syncthreads();
    {   // store: m-row (wp), 256 contiguous d at offset cb*256, rna-rounded
        const int wp = t >> 2, i2 = t & 3;
        const int m  = b * 4096 + hp * 64 + wp;
        float4* dst = (float4*)(g_Xr + (size_t)m * 1024 + cb * 256);
#pragma unroll
        for (int j = 0; j < 16; ++j) {
            int g = j * 4 + i2;               // d-chunk index = row in sm
            dst[g] = cvt4(sm[g * 64 + (wp ^ (g & 7))]);
        }
    }
}

__global__ void __launch_bounds__(256) pre_w(const float* __restrict__ w) {
    const int i = (blockIdx.x * 256 + threadIdx.x) * 4;
    *(float4*)(g_Wr + i) = cvt4(*(const float4*)(w + i));
}

// ======================== tcgen05 cg2 GEMM ==================================

#define TC_THREADS     256
#define TC_TILE_M      512                 // per 2-CTA pair (two M=256 atoms)
#define TC_TILE_N      256
#define TC_NKT         32
#define TC_STAGES      4
#define TC_A_BYTES     (256 * 128)         // per CTA: 2 atoms x 128 rows
#define TC_B_BYTES     (128 * 128)         // per CTA: its 128-row N-half
#define TC_STAGE_BYTES (TC_A_BYTES + TC_B_BYTES)          // 49152
#define TC_SMEM_CTRL   1024
#define TC_SMEM_BYTES  (TC_SMEM_CTRL + TC_STAGES * TC_STAGE_BYTES)   // 197632
#define TC_PAIR_MASK   ((uint16_t)0x3)

// idesc kind::tf32, cg2 M=256 atom: dtype=F32(1)<<4, a/btype=TF32(2),
// n=N>>3 at [17:23), m=M>>4 at [24:29)
#define TC_IDESC  ((1u << 4) | (2u << 7) | (2u << 10) | ((TC_TILE_N / 8) << 17) | ((256 / 16) << 24))
// K-major SW128 desc base: layout=2<<61, version=1<<46, SBO=64<<32, LBO=1<<16
#define TC_DESC_BASE ((2ull << 61) | (1ull << 46) | (64ull << 32) | (1ull << 16))

#if TCGEN05_OK
__device__ __forceinline__ uint64_t make_desc(uint32_t addr) {
    return TC_DESC_BASE | ((uint64_t)(addr >> 4) & 0x3FFF);
}

__device__ __forceinline__ void mma_tf32_cg2(uint32_t d_tmem, uint64_t ad, uint64_t bd,
                                             uint32_t en) {
    asm volatile(
        "{\n\t.reg .pred p;\n\tsetp.ne.u32 p, %4, 0;\n\t"
        "tcgen05.mma.cta_group::2.kind::tf32 [%0], %1, %2, %3, p;\n\t}"
        :: "r"(d_tmem), "l"(ad), "l"(bd), "r"(TC_IDESC), "r"(en) : "memory");
}

__device__ __forceinline__ void mbar_init(uint32_t a, uint32_t cnt) {
    asm volatile("mbarrier.init.shared.b64 [%0], %1;" :: "r"(a), "r"(cnt) : "memory");
}

__device__ __forceinline__ void mbar_wait(uint32_t a, uint32_t parity) {
    uint32_t done;
    asm volatile(
        "{\n\t.reg .pred p;\n\t"
        "mbarrier.try_wait.parity.acquire.cta.shared::cta.b64 p, [%1], %2;\n\t"
        "selp.b32 %0, 1, 0, p;\n\t}"
        : "=r"(done) : "r"(a), "r"(parity) : "memory");
    if (!done) {
        asm volatile(
            "{\n\t.reg .pred P1;\n\t"
            "WL_%=:\n\t"
            "mbarrier.try_wait.parity.acquire.cta.shared::cta.b64 P1, [%0], %1, 0x989680;\n\t"
            "@P1 bra.uni WD_%=;\n\t"
            "bra.uni WL_%=;\n\t"
            "WD_%=:\n\t}"
            :: "r"(a), "r"(parity) : "memory");
    }
}

// cg2 TMA: both CTAs issue; complete_tx targets the LEADER's barrier
// (bit 24 of the barrier address cleared -> peer-pair leader CTA).
__device__ __forceinline__ void tma2d_cg2(uint32_t smem_addr, const void* tmap,
                                          int cx, int cy, uint32_t mbar) {
    asm volatile(
        "{\n\t.reg .b32 lb;\n\t"
        "and.b32 lb, %4, 0xFEFFFFFF;\n\t"
        "cp.async.bulk.tensor.2d.cta_group::2.shared::cluster.global.tile"
        ".mbarrier::complete_tx::bytes [%0], [%1, {%2, %3}], [lb];\n\t}"
        :: "r"(smem_addr), "l"(tmap), "r"(cx), "r"(cy), "r"(mbar) : "memory");
}

#define TC_CLUSTER_SYNC() do { \
    asm volatile("barrier.cluster.arrive.aligned;" ::: "memory"); \
    asm volatile("barrier.cluster.wait.aligned;" ::: "memory"); \
} while (0)
#endif  // TCGEN05_OK

__global__ void __launch_bounds__(TC_THREADS, 1) __cluster_dims__(2, 1, 1)
patch_mix_tc(const __grid_constant__ CUtensorMap tmA,
             const __grid_constant__ CUtensorMap tmB,
             float* __restrict__ y)
{
#if TCGEN05_OK
    extern __shared__ char smem[];
    const uint32_t smem_base = smem_u32(smem);
    const int tid  = threadIdx.x;
    const int warp = tid >> 5;
    const int lane = tid & 31;
    const int rank = blockIdx.x;    // 0..1 : M-half within the pair
    const int bM   = blockIdx.y;    // 0..127 (512-row tiles)
    const int bN   = blockIdx.z;    // 0..3

    // ctrl: [0] tmem ptr; full[s]=64+16s, empty[s]=72+16s (s<4), done=192
    const uint32_t mb_full0  = smem_base + 64;
    const uint32_t mb_empty0 = smem_base + 72;
    const uint32_t mb_done   = smem_base + 192;

    if (warp == 0) {
        asm volatile("tcgen05.alloc.cta_group::2.sync.aligned.shared::cta.b32 [%0], %1;"
                     :: "r"(smem_base), "r"(512u) : "memory");
    }
    if (tid == 0) {
#pragma unroll
        for (int s = 0; s < TC_STAGES; ++s) {
            mbar_init(mb_full0 + 16 * s, 1);   // leader: 1 expect_tx arrival
            mbar_init(mb_empty0 + 16 * s, 1);  // 1 multicast cg2 commit
        }
        mbar_init(mb_done, 1);
    }
    __syncthreads();
    // barriers of BOTH CTAs must exist before any cg2 TMA / multicast commit
    TC_CLUSTER_SYNC();

    uint32_t tmem;
    asm volatile("ld.shared.b32 %0, [%1];" : "=r"(tmem) : "r"(smem_base));

    uint32_t Aaddr[TC_STAGES], Baddr[TC_STAGES];
#pragma unroll
    for (int s = 0; s < TC_STAGES; ++s) {
        Aaddr[s] = smem_base + TC_SMEM_CTRL + s * TC_STAGE_BYTES;
        Baddr[s] = Aaddr[s] + TC_A_BYTES;
    }

    if (warp == 0 && lane == 0) {
        // ---- producer (both ranks): own A-halves of both atoms + own B half
        const int arow0 = bM * TC_TILE_M + rank * 128;        // atom 0
        const int arow1 = bM * TC_TILE_M + 256 + rank * 128;  // atom 1
        const int brow  = bN * TC_TILE_N + rank * 128;        // B N-half
        for (int kt = 0; kt < TC_NKT; ++kt) {
            const int s = kt & 3;
            if (kt >= TC_STAGES)
                mbar_wait(mb_empty0 + 16 * s, ((kt >> 2) - 1) & 1);
            const uint32_t full = mb_full0 + 16 * s;
            if (rank == 0) {
                // expect both CTAs' bytes: 2 x 48 KB
                asm volatile("mbarrier.arrive.expect_tx.shared.b64 _, [%0], %1;"
                             :: "r"(full), "r"((uint32_t)(2 * TC_STAGE_BYTES)) : "memory");
            }
            tma2d_cg2(Aaddr[s],         (const void*)&tmA, kt * 32, arow0, full);
            tma2d_cg2(Aaddr[s] + 16384, (const void*)&tmA, kt * 32, arow1, full);
            tma2d_cg2(Baddr[s],         (const void*)&tmB, kt * 32, brow,  full);
        }
    }
    if (rank == 0 && warp == 1 && lane == 0) {
        // ---- consumer (leader only): cg2 MMAs + multicast commits
        for (int kt = 0; kt < TC_NKT; ++kt) {
            const int s = kt & 3;
            mbar_wait(mb_full0 + 16 * s, (kt >> 2) & 1);
            const uint64_t bD = make_desc(Baddr[s]);
#pragma unroll
            for (int a = 0; a < 2; ++a) {
                const uint64_t aD = make_desc(Aaddr[s] + a * 16384);
#pragma unroll
                for (int ks = 0; ks < 4; ++ks) {
                    mma_tf32_cg2(tmem + a * 256,
                                 aD + ks * 2, bD + ks * 2,
                                 (kt > 0 || ks > 0) ? 1u : 0u);
                }
            }
            asm volatile(
                "tcgen05.commit.cta_group::2.mbarrier::arrive::one.shared::cluster"
                ".multicast::cluster.b64 [%0], %1;"
                :: "r"(mb_empty0 + 16 * s), "h"(TC_PAIR_MASK) : "memory");
            if (kt == TC_NKT - 1) {
                asm volatile(
                    "tcgen05.commit.cta_group::2.mbarrier::arrive::one.shared::cluster"
                    ".multicast::cluster.b64 [%0], %1;"
                    :: "r"(mb_done), "h"(TC_PAIR_MASK) : "memory");
            }
        }
    }

    // ---- all threads (both ranks): wait final MMA completion
    mbar_wait(mb_done, 0);
    asm volatile("tcgen05.fence::after_thread_sync;" ::: "memory");

    // ---- epilogue: this CTA's TMEM = its 128 rows of each atom x 256 cols.
    // warp w: atom a = w>>2 (TMEM col block a*256), partition p = w&3.
    {
        const int a = warp >> 2;
        const int p = warp & 3;
        const uint32_t tm = tmem + a * 256;
        const int mo = bM * TC_TILE_M + a * 256 + rank * 128 + p * 32 + lane;
        const int ob  = mo >> 12;
        const int ohp = (mo >> 6) & 63;
        const int owp = mo & 63;
        float* yb = y + (((size_t)ob) << 22) + (ohp << 10) + owp * 4;

#pragma unroll
        for (int q = 0; q < 8; ++q) {
            uint32_t d[32];
            asm volatile(
                "tcgen05.ld.sync.aligned.32x32b.x32.b32 "
                "{%0,%1,%2,%3,%4,%5,%6,%7,%8,%9,%10,%11,%12,%13,%14,%15,"
                "%16,%17,%18,%19,%20,%21,%22,%23,%24,%25,%26,%27,%28,%29,%30,%31}, [%32];"
                : "=r"(d[0]), "=r"(d[1]), "=r"(d[2]), "=r"(d[3]), "=r"(d[4]), "=r"(d[5]),
                  "=r"(d[6]), "=r"(d[7]), "=r"(d[8]), "=r"(d[9]), "=r"(d[10]), "=r"(d[11]),
                  "=r"(d[12]), "=r"(d[13]), "=r"(d[14]), "=r"(d[15]), "=r"(d[16]), "=r"(d[17]),
                  "=r"(d[18]), "=r"(d[19]), "=r"(d[20]), "=r"(d[21]), "=r"(d[22]), "=r"(d[23]),
                  "=r"(d[24]), "=r"(d[25]), "=r"(d[26]), "=r"(d[27]), "=r"(d[28]), "=r"(d[29]),
                  "=r"(d[30]), "=r"(d[31])
                : "r"(tm + q * 32));
            asm volatile("tcgen05.wait::ld.sync.aligned;" ::: "memory");

            const int ebase = bN * TC_TILE_N + q * 32;
#pragma unroll
            for (int c4 = 0; c4 < 2; ++c4) {
                const int ce = (ebase >> 4) + c4;
#pragma unroll
                for (int ph = 0; ph < 4; ++ph) {
                    float4 o;
                    o.x = __uint_as_float(d[c4 * 16 + ph * 4 + 0]);
                    o.y = __uint_as_float(d[c4 * 16 + ph * 4 + 1]);
                    o.z = __uint_as_float(d[c4 * 16 + ph * 4 + 2]);
                    o.w = __uint_as_float(d[c4 * 16 + ph * 4 + 3]);
                    *(float4*)(yb + (((size_t)ce) << 16) + (ph << 8)) = o;
                }
            }
        }
    }

    asm volatile("tcgen05.fence::before_thread_sync;" ::: "memory");
    __syncthreads();
    if (warp == 0) {
        asm volatile("tcgen05.relinquish_alloc_permit.cta_group::2.sync.aligned;");
        asm volatile("tcgen05.dealloc.cta_group::2.sync.aligned.b32 %0, %1;"
                     :: "r"(tmem), "r"(512u));
    }
    // no CTA may exit while peer ops into its smem/tmem could be in flight
    TC_CLUSTER_SYNC();
#else
    (void)tmA; (void)tmB; (void)y;
#endif
}

// ======================== fallback: proven R1 warp-mma ======================

#define FB_THREADS 256
#define FB_PADK    36
#define FB_ABUF    (128 * FB_PADK)
#define FB_SMEM_BYTES (4 * FB_ABUF * 4)

__device__ __forceinline__ void fb_mma(float d[4], const uint32_t a[4], const uint32_t b[2]) {
    asm volatile(
        "mma.sync.aligned.m16n8k8.row.col.f32.tf32.tf32.f32 "
        "{%0,%1,%2,%3}, {%4,%5,%6,%7}, {%8,%9}, {%0,%1,%2,%3};\n"
        : "+f"(d[0]), "+f"(d[1]), "+f"(d[2]), "+f"(d[3])
        : "r"(a[0]), "r"(a[1]), "r"(a[2]), "r"(a[3]),
          "r"(b[0]), "r"(b[1]));
}

__global__ void __launch_bounds__(FB_THREADS)
patch_mix_fb(const float* __restrict__ x,
             const float* __restrict__ Wm,
             float*       __restrict__ y)
{
    extern __shared__ float smemf[];
    float* As = smemf;
    float* Bs = smemf + 2 * FB_ABUF;

    const int tid  = threadIdx.x;
    const int bN   = blockIdx.x;
    const int bM   = blockIdx.y;

    const int lane = tid & 31;
    const int warp = tid >> 5;
    const int gid  = lane >> 2;
    const int tig  = lane & 3;
    const int wMo  = (warp >> 2) * 64;
    const int wNo  = (warp & 3) * 32;

    const int mA   = tid & 127;
    const int hsel = tid >> 7;

    const int m_g = bM * 128 + mA;
    const int bb  = m_g >> 12;
    const int hp  = (m_g >> 6) & 63;
    const int wp  = m_g & 63;

    const float* pA[4];
    const float* pB[4];
    int sAB[4];
#pragma unroll
    for (int l = 0; l < 4; ++l) {
        int k4   = 2 * l + hsel;
        int coff = k4 >> 2;
        int ph   = k4 & 3;
        pA[l] = x + (((size_t)(bb * 64 + coff)) << 16) + ((hp * 4 + ph) << 8) + wp * 4;
        pB[l] = Wm + (size_t)(bN * 128 + mA) * 1024 + k4 * 4;
        sAB[l] = mA * FB_PADK + k4 * 4;
    }

    float4 av[4], bv[4];
    float acc[4][4][4];
#pragma unroll
    for (int i = 0; i < 4; ++i)
#pragma unroll
        for (int j = 0; j < 4; ++j)
#pragma unroll
            for (int rr = 0; rr < 4; ++rr) acc[i][j][rr] = 0.0f;

#pragma unroll
    for (int l = 0; l < 4; ++l) {
        av[l] = *(const float4*)(pA[l]);
        bv[l] = *(const float4*)(pB[l]);
    }
#pragma unroll
    for (int l = 0; l < 4; ++l) {
        *(float4*)(As + sAB[l]) = cvt4(av[l]);
        *(float4*)(Bs + sAB[l]) = cvt4(bv[l]);
    }
    __syncthreads();

    for (int kt = 0; kt < 32; ++kt) {
        const int cur = kt & 1;
        if (kt < 31) {
#pragma unroll
            for (int l = 0; l < 4; ++l) {
                av[l] = *(const float4*)(pA[l] + (size_t)(kt + 1) * 131072);
                bv[l] = *(const float4*)(pB[l] + (kt + 1) * 32);
            }
        }
        const float* Ab = As + cur * FB_ABUF;
        const float* Bb = Bs + cur * FB_ABUF;
#pragma unroll
        for (int ks = 0; ks < 4; ++ks) {
            uint32_t af[4][4], bf[4][2];
            const int kc = ks * 8 + tig;
#pragma unroll
            for (int mt = 0; mt < 4; ++mt) {
                int rr = wMo + mt * 16 + gid;
                af[mt][0] = __float_as_uint(Ab[rr * FB_PADK + kc]);
                af[mt][1] = __float_as_uint(Ab[(rr + 8) * FB_PADK + kc]);
                af[mt][2] = __float_as_uint(Ab[rr * FB_PADK + kc + 4]);
                af[mt][3] = __float_as_uint(Ab[(rr + 8) * FB_PADK + kc + 4]);
            }
#pragma unroll
            for (int nt = 0; nt < 4; ++nt) {
                int rn = wNo + nt * 8 + gid;
                bf[nt][0] = __float_as_uint(Bb[rn * FB_PADK + kc]);
                bf[nt][1] = __float_as_uint(Bb[rn * FB_PADK + kc + 4]);
            }
#pragma unroll
            for (int mt = 0; mt < 4; ++mt)
#pragma unroll
                for (int nt = 0; nt < 4; ++nt)
                    fb_mma(acc[mt][nt], af[mt], bf[nt]);
        }
        if (kt < 31) {
            const int nxt = cur ^ 1;
#pragma unroll
            for (int l = 0; l < 4; ++l) {
                *(float4*)(As + nxt * FB_ABUF + sAB[l]) = cvt4(av[l]);
                *(float4*)(Bs + nxt * FB_ABUF + sAB[l]) = cvt4(bv[l]);
            }
            __syncthreads();
        }
    }

#pragma unroll
    for (int mt = 0; mt < 4; ++mt) {
#pragma unroll
        for (int h = 0; h < 2; ++h) {
            int m_out = bM * 128 + wMo + mt * 16 + gid + h * 8;
            int ob  = m_out >> 12;
            int ohp = (m_out >> 6) & 63;
            int owp = m_out & 63;
            float* ybase = y + (((size_t)ob) << 22) + (ohp << 10) + owp * 4;
#pragma unroll
            for (int nt = 0; nt < 4; ++nt) {
                int e   = bN * 128 + wNo + nt * 8 + 2 * tig;
                int ce  = e >> 4;
                int oph = (e >> 2) & 3;
                int opw = e & 3;
                float2 vv;
                vv.x = acc[mt][nt][h * 2];
                vv.y = acc[mt][nt][h * 2 + 1];
                *(float2*)(ybase + (ce << 16) + (oph << 8) + opw) = vv;
            }
        }
    }
}

// ======================== dispatch ==========================================

typedef CUresult (*EncodeTiledFn)(
    CUtensorMap*, CUtensorMapDataType, cuuint32_t, void*,
    const cuuint64_t*, const cuuint64_t*, const cuuint32_t*, const cuuint32_t*,
    CUtensorMapInterleave, CUtensorMapSwizzle, CUtensorMapL2promotion,
    CUtensorMapFloatOOBfill);

extern "C" void kernel_launch(void* const* d_in, const int* in_sizes, int n_in,
                              void* d_out, int out_size)
{
    const float* x  = (const float*)d_in[0];
    const float* Wm = (const float*)d_in[1];
    float*       y  = (float*)d_out;

    cudaFuncAttributes attr{};
    bool use_tc = false;
    if (cudaFuncGetAttributes(&attr, (const void*)patch_mix_tc) == cudaSuccess)
        use_tc = (attr.numRegs >= 40);

    EncodeTiledFn encode = nullptr;
    void* xr = nullptr;
    void* wr = nullptr;
    if (use_tc) {
        cudaDriverEntryPointQueryResult st;
        void* fn = nullptr;
        if (cudaGetDriverEntryPoint("cuTensorMapEncodeTiled", &fn,
                                    cudaEnableDefault, &st) == cudaSuccess &&
            st == cudaDriverEntryPointSuccess)
            encode = (EncodeTiledFn)fn;
        if (!encode ||
            cudaGetSymbolAddress(&xr, g_Xr) != cudaSuccess ||
            cudaGetSymbolAddress(&wr, g_Wr) != cudaSuccess)
            use_tc = false;
    }

    CUtensorMap tmA{}, tmB{};
    if (use_tc) {
        cuuint64_t dimsA[2]    = {1024, 65536};
        cuuint64_t strideA[1]  = {1024 * 4};
        cuuint32_t box128[2]   = {32, 128};    // 32 f32 x 128 rows (both A and B)
        cuuint32_t es[2]       = {1, 1};
        cuuint64_t dimsB[2]    = {1024, 1024};
        cuuint64_t strideB[1]  = {1024 * 4};
        if (encode(&tmA, CU_TENSOR_MAP_DATA_TYPE_FLOAT32, 2, xr, dimsA, strideA,
                   box128, es, CU_TENSOR_MAP_INTERLEAVE_NONE, CU_TENSOR_MAP_SWIZZLE_128B,
                   CU_TENSOR_MAP_L2_PROMOTION_L2_128B,
                   CU_TENSOR_MAP_FLOAT_OOB_FILL_NONE) != CUDA_SUCCESS)
            use_tc = false;
        else if (encode(&tmB, CU_TENSOR_MAP_DATA_TYPE_FLOAT32, 2, wr, dimsB, strideB,
                        box128, es, CU_TENSOR_MAP_INTERLEAVE_NONE, CU_TENSOR_MAP_SWIZZLE_128B,
                        CU_TENSOR_MAP_L2_PROMOTION_L2_128B,
                        CU_TENSOR_MAP_FLOAT_OOB_FILL_NONE) != CUDA_SUCCESS)
            use_tc = false;
    }

    if (use_tc) {
        cudaFuncSetAttribute(pre_x, cudaFuncAttributeMaxDynamicSharedMemorySize, 65536);
        cudaFuncSetAttribute(patch_mix_tc,
                             cudaFuncAttributeMaxDynamicSharedMemorySize, TC_SMEM_BYTES);
        pre_x<<<4096, 256, 65536>>>(x);
        pre_w<<<1024, 256>>>(Wm);
        dim3 grid(2, 128, 4);   // (rank, bM512, bN) — cluster (2,1,1) along x
        patch_mix_tc<<<grid, TC_THREADS, TC_SMEM_BYTES>>>(tmA, tmB, y);
    } else {
        cudaFuncSetAttribute(patch_mix_fb,
                             cudaFuncAttributeMaxDynamicSharedMemorySize, FB_SMEM_BYTES);
        dim3 grid(8, 512);
        patch_mix_fb<<<grid, FB_THREADS, FB_SMEM_BYTES>>>(x, Wm, y);
    }
}

// round 12
// speedup vs baseline: 1.2169x; 1.2169x over previous
#include <cuda_runtime.h>
#include <cuda.h>
#include <cstdint>

// ----------------------------------------------------------------------------
// BasePatchOrthogonalMix as one GEMM: out[m,e] = sum_d patch[m,d] * W[e,d]
//   m = (b,hp,wp) = 65536,  d/e = (c,ph,pw) = 1024
//
// R10:
//  * GEMM: exact revert to the proven R6 single-CTA tcgen05 pipeline (187 us).
//    Both cluster variants (csz4 TMA-MC, cg2) regressed: cross-CTA coupling
//    costs more than the LTS bytes they save. Only change: A TMA is 3D over
//    the new tiled scratch layout.
//  * pre_x: NEW smem-free streaming version. Scratch layout g_Xr[kt][m][32]
//    (K-tile-tiled) makes BOTH the gather read and the rounded write fully
//    coalesced -> no transpose, no smem, no syncthreads. 96 -> ~72 us.
//  * cvt.rna.tf32 in pre-pass (truncation bias ~2^-10 > 1e-3 budget).
//  Fallback warp-mma kernel + numRegs dispatch retained.
// ----------------------------------------------------------------------------

#if defined(__CUDA_ARCH__) && (defined(__CUDA_ARCH_FEAT_SM103_ALL) || defined(__CUDA_ARCH_FEAT_SM100_ALL))
#define TCGEN05_OK 1
#else
#define TCGEN05_OK 0
#endif

// Scratch: A as [kt(32)][m(65536)][32 floats] (128 B rows), W row-major.
__device__ float g_Xr[65536ull * 1024];
__device__ float g_Wr[1024 * 1024];

// ======================== common helpers ====================================

__device__ __forceinline__ uint32_t f2tf32(float f) {
    uint32_t u;
    asm("cvt.rna.tf32.f32 %0, %1;" : "=r"(u) : "f"(f));
    return u;
}

__device__ __forceinline__ float4 cvt4(float4 v) {
    float4 t;
    t.x = __uint_as_float(f2tf32(v.x));
    t.y = __uint_as_float(f2tf32(v.y));
    t.z = __uint_as_float(f2tf32(v.z));
    t.w = __uint_as_float(f2tf32(v.w));
    return t;
}

__device__ __forceinline__ uint32_t smem_u32(const void* p) {
    uint32_t a;
    asm("{ .reg .u64 t; cvta.to.shared.u64 t, %1; cvt.u32.u64 %0, t; }" : "=r"(a) : "l"(p));
    return a;
}

// ======================== pre-pass kernels ==================================

// pre_x: CTA (bx=m-block of 256, by=kt-group of 8). Thread t: j = t&7 (16B
// d-chunk within the 32-float K tile), ml = t>>3 (m within 32-row slab).
//  read : lanes sharing j have consecutive wp -> 64B segments (coalesced)
//  write: warp covers 4 m x 8 j = 512B contiguous (fully coalesced)
__global__ void __launch_bounds__(256) pre_x(const float* __restrict__ x) {
    const int t    = threadIdx.x;
    const int j    = t & 7;
    const int ml   = t >> 3;
    const int m0   = blockIdx.x * 256;
    const int kt0  = blockIdx.y * 8;
    const int coff = j >> 2;     // channel offset within K tile (0/1)
    const int ph   = j & 3;

#pragma unroll
    for (int mb = 0; mb < 8; ++mb) {
        const int m  = m0 + mb * 32 + ml;
        const int b  = m >> 12;
        const int hp = (m >> 6) & 63;
        const int wp = m & 63;
        // x[b][c][hp*4+ph][wp*4 .. +4), c = kt*2 + coff
        const float* src = x + (((size_t)b) << 22) + (((size_t)coff) << 16)
                             + (hp << 10) + (ph << 8) + wp * 4;
        float* dst = g_Xr + (size_t)kt0 * 2097152 + (size_t)m * 32 + j * 4;
#pragma unroll
        for (int k = 0; k < 8; ++k) {
            float4 v = *(const float4*)(src + ((size_t)(kt0 + k)) * 131072);
            *(float4*)(dst + (size_t)k * 2097152) = cvt4(v);
        }
    }
}

__global__ void __launch_bounds__(256) pre_w(const float* __restrict__ w) {
    const int i = (blockIdx.x * 256 + threadIdx.x) * 4;
    *(float4*)(g_Wr + i) = cvt4(*(const float4*)(w + i));
}

// ======================== tcgen05 GEMM (R6 design) ==========================

#define TC_THREADS     256
#define TC_TILE_M      256
#define TC_TILE_N      256
#define TC_NKT         32
#define TC_STAGES      3
#define TC_A_BYTES     (TC_TILE_M * 128)
#define TC_B_BYTES     (TC_TILE_N * 128)
#define TC_STAGE_BYTES (TC_A_BYTES + TC_B_BYTES)          // 65536
#define TC_SMEM_CTRL   1024
#define TC_SMEM_BYTES  (TC_SMEM_CTRL + TC_STAGES * TC_STAGE_BYTES)   // 197632

// idesc kind::tf32: dtype=F32(1)<<4, atype=TF32(2)<<7, btype=TF32(2)<<10,
// n_dim=N>>3 at [17:23), m_dim=M>>4 at [24:29) (M=128 per MMA)
#define TC_IDESC  ((1u << 4) | (2u << 7) | (2u << 10) | ((TC_TILE_N / 8) << 17) | ((128 / 16) << 24))
// K-major SW128 desc base: layout=2<<61, version=1<<46, SBO=64<<32, LBO=1<<16
#define TC_DESC_BASE ((2ull << 61) | (1ull << 46) | (64ull << 32) | (1ull << 16))

#if TCGEN05_OK
__device__ __forceinline__ uint64_t make_desc(uint32_t addr) {
    return TC_DESC_BASE | ((uint64_t)(addr >> 4) & 0x3FFF);
}

__device__ __forceinline__ void mma_tf32_ss(uint32_t d_tmem, uint64_t ad, uint64_t bd,
                                            uint32_t en) {
    asm volatile(
        "{\n\t.reg .pred p;\n\tsetp.ne.u32 p, %4, 0;\n\t"
        "tcgen05.mma.cta_group::1.kind::tf32 [%0], %1, %2, %3, p;\n\t}"
        :: "r"(d_tmem), "l"(ad), "l"(bd), "r"(TC_IDESC), "r"(en) : "memory");
}

__device__ __forceinline__ void mbar_init(uint32_t a, uint32_t cnt) {
    asm volatile("mbarrier.init.shared.b64 [%0], %1;" :: "r"(a), "r"(cnt) : "memory");
}

__device__ __forceinline__ void mbar_wait(uint32_t a, uint32_t parity) {
    uint32_t done;
    asm volatile(
        "{\n\t.reg .pred p;\n\t"
        "mbarrier.try_wait.parity.acquire.cta.shared::cta.b64 p, [%1], %2;\n\t"
        "selp.b32 %0, 1, 0, p;\n\t}"
        : "=r"(done) : "r"(a), "r"(parity) : "memory");
    if (!done) {
        asm volatile(
            "{\n\t.reg .pred P1;\n\t"
            "WL_%=:\n\t"
            "mbarrier.try_wait.parity.acquire.cta.shared::cta.b64 P1, [%0], %1, 0x989680;\n\t"
            "@P1 bra.uni WD_%=;\n\t"
            "bra.uni WL_%=;\n\t"
            "WD_%=:\n\t}"
            :: "r"(a), "r"(parity) : "memory");
    }
}

__device__ __forceinline__ void tma2d(uint32_t smem_addr, const void* tmap,
                                      int cx, int cy, uint32_t mbar) {
    asm volatile(
        "cp.async.bulk.tensor.2d.shared::cta.global.tile.mbarrier::complete_tx::bytes "
        "[%0], [%1, {%2, %3}], [%4];"
        :: "r"(smem_addr), "l"(tmap), "r"(cx), "r"(cy), "r"(mbar) : "memory");
}

__device__ __forceinline__ void tma3d(uint32_t smem_addr, const void* tmap,
                                      int cx, int cy, int cz, uint32_t mbar) {
    asm volatile(
        "cp.async.bulk.tensor.3d.shared::cta.global.tile.mbarrier::complete_tx::bytes "
        "[%0], [%1, {%2, %3, %4}], [%5];"
        :: "r"(smem_addr), "l"(tmap), "r"(cx), "r"(cy), "r"(cz), "r"(mbar) : "memory");
}
#endif  // TCGEN05_OK

__global__ void __launch_bounds__(TC_THREADS, 1)
patch_mix_tc(const __grid_constant__ CUtensorMap tmA,
             const __grid_constant__ CUtensorMap tmB,
             float* __restrict__ y)
{
#if TCGEN05_OK
    extern __shared__ char smem[];
    const uint32_t smem_base = smem_u32(smem);
    const int tid  = threadIdx.x;
    const int warp = tid >> 5;
    const int lane = tid & 31;
    const int bN   = blockIdx.x;   // 0..3
    const int bM   = blockIdx.y;   // 0..255

    // ctrl: [0] tmem ptr; mbarriers: full[s]=64+16s, empty[s]=72+16s, done=160
    const uint32_t mb_full0  = smem_base + 64;
    const uint32_t mb_empty0 = smem_base + 72;
    const uint32_t mb_done   = smem_base + 160;

    if (warp == 0) {
        asm volatile("tcgen05.alloc.cta_group::1.sync.aligned.shared::cta.b32 [%0], %1;"
                     :: "r"(smem_base), "r"(512u) : "memory");
    }
    if (tid == 0) {
#pragma unroll
        for (int s = 0; s < TC_STAGES; ++s) {
            mbar_init(mb_full0 + 16 * s, 1);
            mbar_init(mb_empty0 + 16 * s, 1);
        }
        mbar_init(mb_done, 1);
    }
    __syncthreads();
    uint32_t tmem;
    asm volatile("ld.shared.b32 %0, [%1];" : "=r"(tmem) : "r"(smem_base));

    uint32_t Aaddr[TC_STAGES], Baddr[TC_STAGES];
#pragma unroll
    for (int s = 0; s < TC_STAGES; ++s) {
        Aaddr[s] = smem_base + TC_SMEM_CTRL + s * TC_STAGE_BYTES;
        Baddr[s] = Aaddr[s] + TC_A_BYTES;
    }

    if (warp == 0 && lane == 0) {
        // -------- producer: TMA, runs up to 3 tiles ahead
        for (int kt = 0; kt < TC_NKT; ++kt) {
            const int s = kt % TC_STAGES;
            if (kt >= TC_STAGES)
                mbar_wait(mb_empty0 + 16 * s, ((kt / TC_STAGES) - 1) & 1);
            const uint32_t full = mb_full0 + 16 * s;
            asm volatile("mbarrier.arrive.expect_tx.shared.b64 _, [%0], %1;"
                         :: "r"(full), "r"((uint32_t)TC_STAGE_BYTES) : "memory");
            // A: tiled scratch [kt][m][32]: coords (0, m_row, kt)
            tma3d(Aaddr[s], (const void*)&tmA, 0, bM * TC_TILE_M, kt, full);
            tma2d(Baddr[s], (const void*)&tmB, kt * 32, bN * TC_TILE_N, full);
        }
    }
    if (warp == 1 && lane == 0) {
        // -------- consumer: MMA issue + commits
        for (int kt = 0; kt < TC_NKT; ++kt) {
            const int s = kt % TC_STAGES;
            mbar_wait(mb_full0 + 16 * s, (kt / TC_STAGES) & 1);
            const uint64_t aD = make_desc(Aaddr[s]);
            const uint64_t bD = make_desc(Baddr[s]);
#pragma unroll
            for (int h = 0; h < 2; ++h) {
#pragma unroll
                for (int ks = 0; ks < 4; ++ks) {
                    mma_tf32_ss(tmem + h * 256,
                                aD + h * 1024 + ks * 2,   // +128 rows = +1024 units
                                bD + ks * 2,
                                (kt > 0 || ks > 0) ? 1u : 0u);
                }
            }
            asm volatile(
                "tcgen05.commit.cta_group::1.mbarrier::arrive::one.shared::cluster.b64 [%0];"
                :: "r"(mb_empty0 + 16 * s) : "memory");
            if (kt == TC_NKT - 1) {
                asm volatile(
                    "tcgen05.commit.cta_group::1.mbarrier::arrive::one.shared::cluster.b64 [%0];"
                    :: "r"(mb_done) : "memory");
            }
        }
    }

    // -------- all threads: wait for final MMA completion
    mbar_wait(mb_done, 0);
    asm volatile("tcgen05.fence::after_thread_sync;" ::: "memory");

    // -------- epilogue: 8 warps. h = M-half (warp>>2), p = lane partition (warp&3)
    {
        const int p = warp & 3;
        const int h = warp >> 2;
        const uint32_t tm = tmem + h * 256;
        const int mo = bM * TC_TILE_M + h * 128 + p * 32 + lane;
        const int ob  = mo >> 12;
        const int ohp = (mo >> 6) & 63;
        const int owp = mo & 63;
        float* yb = y + (((size_t)ob) << 22) + (ohp << 10) + owp * 4;

#pragma unroll
        for (int q = 0; q < 8; ++q) {
            uint32_t d[32];
            asm volatile(
                "tcgen05.ld.sync.aligned.32x32b.x32.b32 "
                "{%0,%1,%2,%3,%4,%5,%6,%7,%8,%9,%10,%11,%12,%13,%14,%15,"
                "%16,%17,%18,%19,%20,%21,%22,%23,%24,%25,%26,%27,%28,%29,%30,%31}, [%32];"
                : "=r"(d[0]), "=r"(d[1]), "=r"(d[2]), "=r"(d[3]), "=r"(d[4]), "=r"(d[5]),
                  "=r"(d[6]), "=r"(d[7]), "=r"(d[8]), "=r"(d[9]), "=r"(d[10]), "=r"(d[11]),
                  "=r"(d[12]), "=r"(d[13]), "=r"(d[14]), "=r"(d[15]), "=r"(d[16]), "=r"(d[17]),
                  "=r"(d[18]), "=r"(d[19]), "=r"(d[20]), "=r"(d[21]), "=r"(d[22]), "=r"(d[23]),
                  "=r"(d[24]), "=r"(d[25]), "=r"(d[26]), "=r"(d[27]), "=r"(d[28]), "=r"(d[29]),
                  "=r"(d[30]), "=r"(d[31])
                : "r"(tm + q * 32));
            asm volatile("tcgen05.wait::ld.sync.aligned;" ::: "memory");

            const int ebase = bN * TC_TILE_N + q * 32;
#pragma unroll
            for (int c4 = 0; c4 < 2; ++c4) {
                const int ce = (ebase >> 4) + c4;
#pragma unroll
                for (int ph = 0; ph < 4; ++ph) {
                    float4 o;
                    o.x = __uint_as_float(d[c4 * 16 + ph * 4 + 0]);
                    o.y = __uint_as_float(d[c4 * 16 + ph * 4 + 1]);
                    o.z = __uint_as_float(d[c4 * 16 + ph * 4 + 2]);
                    o.w = __uint_as_float(d[c4 * 16 + ph * 4 + 3]);
                    *(float4*)(yb + (((size_t)ce) << 16) + (ph << 8)) = o;
                }
            }
        }
    }

    asm volatile("tcgen05.fence::before_thread_sync;" ::: "memory");
    __syncthreads();
    if (warp == 0) {
        asm volatile("tcgen05.relinquish_alloc_permit.cta_group::1.sync.aligned;");
        asm volatile("tcgen05.dealloc.cta_group::1.sync.aligned.b32 %0, %1;"
                     :: "r"(tmem), "r"(512u));
    }
#else
    (void)tmA; (void)tmB; (void)y;
#endif
}

// ======================== fallback: proven R1 warp-mma ======================

#define FB_THREADS 256
#define FB_PADK    36
#define FB_ABUF    (128 * FB_PADK)
#define FB_SMEM_BYTES (4 * FB_ABUF * 4)

__device__ __forceinline__ void fb_mma(float d[4], const uint32_t a[4], const uint32_t b[2]) {
    asm volatile(
        "mma.sync.aligned.m16n8k8.row.col.f32.tf32.tf32.f32 "
        "{%0,%1,%2,%3}, {%4,%5,%6,%7}, {%8,%9}, {%0,%1,%2,%3};\n"
        : "+f"(d[0]), "+f"(d[1]), "+f"(d[2]), "+f"(d[3])
        : "r"(a[0]), "r"(a[1]), "r"(a[2]), "r"(a[3]),
          "r"(b[0]), "r"(b[1]));
}

__global__ void __launch_bounds__(FB_THREADS)
patch_mix_fb(const float* __restrict__ x,
             const float* __restrict__ Wm,
             float*       __restrict__ y)
{
    extern __shared__ float smemf[];
    float* As = smemf;
    float* Bs = smemf + 2 * FB_ABUF;

    const int tid  = threadIdx.x;
    const int bN   = blockIdx.x;
    const int bM   = blockIdx.y;

    const int lane = tid & 31;
    const int warp = tid >> 5;
    const int gid  = lane >> 2;
    const int tig  = lane & 3;
    const int wMo  = (warp >> 2) * 64;
    const int wNo  = (warp & 3) * 32;

    const int mA   = tid & 127;
    const int hsel = tid >> 7;

    const int m_g = bM * 128 + mA;
    const int bb  = m_g >> 12;
    const int hp  = (m_g >> 6) & 63;
    const int wp  = m_g & 63;

    const float* pA[4];
    const float* pB[4];
    int sAB[4];
#pragma unroll
    for (int l = 0; l < 4; ++l) {
        int k4   = 2 * l + hsel;
        int coff = k4 >> 2;
        int ph   = k4 & 3;
        pA[l] = x + (((size_t)(bb * 64 + coff)) << 16) + ((hp * 4 + ph) << 8) + wp * 4;
        pB[l] = Wm + (size_t)(bN * 128 + mA) * 1024 + k4 * 4;
        sAB[l] = mA * FB_PADK + k4 * 4;
    }

    float4 av[4], bv[4];
    float acc[4][4][4];
#pragma unroll
    for (int i = 0; i < 4; ++i)
#pragma unroll
        for (int j = 0; j < 4; ++j)
#pragma unroll
            for (int rr = 0; rr < 4; ++rr) acc[i][j][rr] = 0.0f;

#pragma unroll
    for (int l = 0; l < 4; ++l) {
        av[l] = *(const float4*)(pA[l]);
        bv[l] = *(const float4*)(pB[l]);
    }
#pragma unroll
    for (int l = 0; l < 4; ++l) {
        *(float4*)(As + sAB[l]) = cvt4(av[l]);
        *(float4*)(Bs + sAB[l]) = cvt4(bv[l]);
    }
    __syncthreads();

    for (int kt = 0; kt < 32; ++kt) {
        const int cur = kt & 1;
        if (kt < 31) {
#pragma unroll
            for (int l = 0; l < 4; ++l) {
                av[l] = *(const float4*)(pA[l] + (size_t)(kt + 1) * 131072);
                bv[l] = *(const float4*)(pB[l] + (kt + 1) * 32);
            }
        }
        const float* Ab = As + cur * FB_ABUF;
        const float* Bb = Bs + cur * FB_ABUF;
#pragma unroll
        for (int ks = 0; ks < 4; ++ks) {
            uint32_t af[4][4], bf[4][2];
            const int kc = ks * 8 + tig;
#pragma unroll
            for (int mt = 0; mt < 4; ++mt) {
                int rr = wMo + mt * 16 + gid;
                af[mt][0] = __float_as_uint(Ab[rr * FB_PADK + kc]);
                af[mt][1] = __float_as_uint(Ab[(rr + 8) * FB_PADK + kc]);
                af[mt][2] = __float_as_uint(Ab[rr * FB_PADK + kc + 4]);
                af[mt][3] = __float_as_uint(Ab[(rr + 8) * FB_PADK + kc + 4]);
            }
#pragma unroll
            for (int nt = 0; nt < 4; ++nt) {
                int rn = wNo + nt * 8 + gid;
                bf[nt][0] = __float_as_uint(Bb[rn * FB_PADK + kc]);
                bf[nt][1] = __float_as_uint(Bb[rn * FB_PADK + kc + 4]);
            }
#pragma unroll
            for (int mt = 0; mt < 4; ++mt)
#pragma unroll
                for (int nt = 0; nt < 4; ++nt)
                    fb_mma(acc[mt][nt], af[mt], bf[nt]);
        }
        if (kt < 31) {
            const int nxt = cur ^ 1;
#pragma unroll
            for (int l = 0; l < 4; ++l) {
                *(float4*)(As + nxt * FB_ABUF + sAB[l]) = cvt4(av[l]);
                *(float4*)(Bs + nxt * FB_ABUF + sAB[l]) = cvt4(bv[l]);
            }
            __syncthreads();
        }
    }

#pragma unroll
    for (int mt = 0; mt < 4; ++mt) {
#pragma unroll
        for (int h = 0; h < 2; ++h) {
            int m_out = bM * 128 + wMo + mt * 16 + gid + h * 8;
            int ob  = m_out >> 12;
            int ohp = (m_out >> 6) & 63;
            int owp = m_out & 63;
            float* ybase = y + (((size_t)ob) << 22) + (ohp << 10) + owp * 4;
#pragma unroll
            for (int nt = 0; nt < 4; ++nt) {
                int e   = bN * 128 + wNo + nt * 8 + 2 * tig;
                int ce  = e >> 4;
                int oph = (e >> 2) & 3;
                int opw = e & 3;
                float2 vv;
                vv.x = acc[mt][nt][h * 2];
                vv.y = acc[mt][nt][h * 2 + 1];
                *(float2*)(ybase + (ce << 16) + (oph << 8) + opw) = vv;
            }
        }
    }
}

// ======================== dispatch ==========================================

typedef CUresult (*EncodeTiledFn)(
    CUtensorMap*, CUtensorMapDataType, cuuint32_t, void*,
    const cuuint64_t*, const cuuint64_t*, const cuuint32_t*, const cuuint32_t*,
    CUtensorMapInterleave, CUtensorMapSwizzle, CUtensorMapL2promotion,
    CUtensorMapFloatOOBfill);

extern "C" void kernel_launch(void* const* d_in, const int* in_sizes, int n_in,
                              void* d_out, int out_size)
{
    const float* x  = (const float*)d_in[0];
    const float* Wm = (const float*)d_in[1];
    float*       y  = (float*)d_out;

    cudaFuncAttributes attr{};
    bool use_tc = false;
    if (cudaFuncGetAttributes(&attr, (const void*)patch_mix_tc) == cudaSuccess)
        use_tc = (attr.numRegs >= 40);

    EncodeTiledFn encode = nullptr;
    void* xr = nullptr;
    void* wr = nullptr;
    if (use_tc) {
        cudaDriverEntryPointQueryResult st;
        void* fn = nullptr;
        if (cudaGetDriverEntryPoint("cuTensorMapEncodeTiled", &fn,
                                    cudaEnableDefault, &st) == cudaSuccess &&
            st == cudaDriverEntryPointSuccess)
            encode = (EncodeTiledFn)fn;
        if (!encode ||
            cudaGetSymbolAddress(&xr, g_Xr) != cudaSuccess ||
            cudaGetSymbolAddress(&wr, g_Wr) != cudaSuccess)
            use_tc = false;
    }

    CUtensorMap tmA{}, tmB{};
    if (use_tc) {
        // A tiled: [32 floats][65536 m][32 kt]; row = 128 B, plane = 8 MB
        cuuint64_t dimsA[3]    = {32, 65536, 32};
        cuuint64_t strideA[2]  = {128, 65536ull * 128};
        cuuint32_t boxA[3]     = {32, 256, 1};
        cuuint32_t esA[3]      = {1, 1, 1};
        cuuint64_t dimsB[2]    = {1024, 1024};
        cuuint64_t strideB[1]  = {1024 * 4};
        cuuint32_t boxB[2]     = {32, 256};
        cuuint32_t esB[2]      = {1, 1};
        if (encode(&tmA, CU_TENSOR_MAP_DATA_TYPE_FLOAT32, 3, xr, dimsA, strideA,
                   boxA, esA, CU_TENSOR_MAP_INTERLEAVE_NONE, CU_TENSOR_MAP_SWIZZLE_128B,
                   CU_TENSOR_MAP_L2_PROMOTION_L2_128B,
                   CU_TENSOR_MAP_FLOAT_OOB_FILL_NONE) != CUDA_SUCCESS)
            use_tc = false;
        else if (encode(&tmB, CU_TENSOR_MAP_DATA_TYPE_FLOAT32, 2, wr, dimsB, strideB,
                        boxB, esB, CU_TENSOR_MAP_INTERLEAVE_NONE, CU_TENSOR_MAP_SWIZZLE_128B,
                        CU_TENSOR_MAP_L2_PROMOTION_L2_128B,
                        CU_TENSOR_MAP_FLOAT_OOB_FILL_NONE) != CUDA_SUCCESS)
            use_tc = false;
    }

    if (use_tc) {
        cudaFuncSetAttribute(patch_mix_tc,
                             cudaFuncAttributeMaxDynamicSharedMemorySize, TC_SMEM_BYTES);
        dim3 pgrid(256, 4);      // 256 m-blocks x 4 kt-groups
        pre_x<<<pgrid, 256>>>(x);
        pre_w<<<1024, 256>>>(Wm);
        dim3 grid(4, 256);       // N inner: 4 CTAs per bM row share A tile in L2
        patch_mix_tc<<<grid, TC_THREADS, TC_SMEM_BYTES>>>(tmA, tmB, y);
    } else {
        cudaFuncSetAttribute(patch_mix_fb,
                             cudaFuncAttributeMaxDynamicSharedMemorySize, FB_SMEM_BYTES);
        dim3 grid(8, 512);
        patch_mix_fb<<<grid, FB_THREADS, FB_SMEM_BYTES>>>(x, Wm, y);
    }
}

// round 13
// speedup vs baseline: 1.2377x; 1.0171x over previous
#include <cuda_runtime.h>
#include <cuda.h>
#include <cstdint>

// ----------------------------------------------------------------------------
// BasePatchOrthogonalMix as one GEMM: out[m,e] = sum_d patch[m,d] * W[e,d]
//   m = (b,hp,wp) = 65536,  d/e = (c,ph,pw) = 1024
//
// R12:
//  * GEMM: exact R6 config (proven ~186 us): single-CTA tcgen05 tf32,
//    256x256xK32, TMEM accum, 3-stage TMA ring, row-major g_Xr + 2D TMA.
//  * pre_x: smem transpose (R7 structure, XOR swizzle, 4-way optimal) with
//    tile HALVED to 32 KB -> 7 CTAs/SM (occ 36% -> ~85%) for DRAM latency
//    hiding. grid 8192.
//  * cvt.rna.tf32 in pre-pass (truncation bias ~2^-10 > 1e-3 budget).
//  Fallback warp-mma kernel + numRegs dispatch retained.
// ----------------------------------------------------------------------------

#if defined(__CUDA_ARCH__) && (defined(__CUDA_ARCH_FEAT_SM103_ALL) || defined(__CUDA_ARCH_FEAT_SM100_ALL))
#define TCGEN05_OK 1
#else
#define TCGEN05_OK 0
#endif

// Scratch: A row-major [65536 x 1024], W row-major [1024 x 1024].
__device__ float g_Xr[65536ull * 1024];
__device__ float g_Wr[1024 * 1024];

// ======================== common helpers ====================================

__device__ __forceinline__ uint32_t f2tf32(float f) {
    uint32_t u;
    asm("cvt.rna.tf32.f32 %0, %1;" : "=r"(u) : "f"(f));
    return u;
}

__device__ __forceinline__ float4 cvt4(float4 v) {
    float4 t;
    t.x = __uint_as_float(f2tf32(v.x));
    t.y = __uint_as_float(f2tf32(v.y));
    t.z = __uint_as_float(f2tf32(v.z));
    t.w = __uint_as_float(f2tf32(v.w));
    return t;
}

__device__ __forceinline__ uint32_t smem_u32(const void* p) {
    uint32_t a;
    asm("{ .reg .u64 t; cvta.to.shared.u64 t, %1; cvt.u32.u64 %0, t; }" : "=r"(a) : "l"(p));
    return a;
}

// ======================== pre-pass kernels ==================================

// pre_x: CTA = (b, hp, cb8): 8 channels x 4 ph x 256 w -> 64 m-rows x 128 d.
// smem: 32 rows x 64 float4 = 32 KB, XOR swizzle col4' = col4 ^ (row & 7).
// Both gmem phases coalesced (128 B read rows, 64 B write segments);
// smem 4-way on both phases (optimal for 16 B accesses).
__global__ void __launch_bounds__(256) pre_x(const float* __restrict__ x) {
    extern __shared__ float4 sm[];   // 32 * 64 float4 = 32 KB
    const int t   = threadIdx.x;
    const int cb8 = blockIdx.x & 7;          // 8-channel block
    const int hp  = (blockIdx.x >> 3) & 63;
    const int b   = blockIdx.x >> 9;

    {   // load: row r = c2*4+ph (c2 0..7), 256 floats of x[b][cb8*8+c2][hp*4+ph][:]
        const int r = t >> 3, i = t & 7;
        const int c  = cb8 * 8 + (r >> 2);
        const int ph = r & 3;
        const float4* src = (const float4*)(x + (((size_t)(b * 64 + c)) << 16)
                                              + ((hp * 4 + ph) << 8));
#pragma unroll
        for (int jj = 0; jj < 8; ++jj) {
            int f = jj * 8 + i;
            sm[r * 64 + (f ^ (r & 7))] = src[f];
        }
    }
    __syncthreads();
    {   // store: m-row (wp), 128 contiguous d at offset cb8*128, rna-rounded
        const int wp = t >> 2, i2 = t & 3;
        const int m  = b * 4096 + hp * 64 + wp;
        float4* dst = (float4*)(g_Xr + (size_t)m * 1024 + cb8 * 128);
#pragma unroll
        for (int jj = 0; jj < 8; ++jj) {
            int g = jj * 4 + i2;             // chunk g = c2*4+ph = smem row
            dst[g] = cvt4(sm[g * 64 + (wp ^ (g & 7))]);
        }
    }
}

__global__ void __launch_bounds__(256) pre_w(const float* __restrict__ w) {
    const int i = (blockIdx.x * 256 + threadIdx.x) * 4;
    *(float4*)(g_Wr + i) = cvt4(*(const float4*)(w + i));
}

// ======================== tcgen05 GEMM (R6 design) ==========================

#define TC_THREADS     256
#define TC_TILE_M      256
#define TC_TILE_N      256
#define TC_NKT         32
#define TC_STAGES      3
#define TC_A_BYTES     (TC_TILE_M * 128)
#define TC_B_BYTES     (TC_TILE_N * 128)
#define TC_STAGE_BYTES (TC_A_BYTES + TC_B_BYTES)          // 65536
#define TC_SMEM_CTRL   1024
#define TC_SMEM_BYTES  (TC_SMEM_CTRL + TC_STAGES * TC_STAGE_BYTES)   // 197632

// idesc kind::tf32: dtype=F32(1)<<4, atype=TF32(2)<<7, btype=TF32(2)<<10,
// n_dim=N>>3 at [17:23), m_dim=M>>4 at [24:29) (M=128 per MMA)
#define TC_IDESC  ((1u << 4) | (2u << 7) | (2u << 10) | ((TC_TILE_N / 8) << 17) | ((128 / 16) << 24))
// K-major SW128 desc base: layout=2<<61, version=1<<46, SBO=64<<32, LBO=1<<16
#define TC_DESC_BASE ((2ull << 61) | (1ull << 46) | (64ull << 32) | (1ull << 16))

#if TCGEN05_OK
__device__ __forceinline__ uint64_t make_desc(uint32_t addr) {
    return TC_DESC_BASE | ((uint64_t)(addr >> 4) & 0x3FFF);
}

__device__ __forceinline__ void mma_tf32_ss(uint32_t d_tmem, uint64_t ad, uint64_t bd,
                                            uint32_t en) {
    asm volatile(
        "{\n\t.reg .pred p;\n\tsetp.ne.u32 p, %4, 0;\n\t"
        "tcgen05.mma.cta_group::1.kind::tf32 [%0], %1, %2, %3, p;\n\t}"
        :: "r"(d_tmem), "l"(ad), "l"(bd), "r"(TC_IDESC), "r"(en) : "memory");
}

__device__ __forceinline__ void mbar_init(uint32_t a, uint32_t cnt) {
    asm volatile("mbarrier.init.shared.b64 [%0], %1;" :: "r"(a), "r"(cnt) : "memory");
}

__device__ __forceinline__ void mbar_wait(uint32_t a, uint32_t parity) {
    uint32_t done;
    asm volatile(
        "{\n\t.reg .pred p;\n\t"
        "mbarrier.try_wait.parity.acquire.cta.shared::cta.b64 p, [%1], %2;\n\t"
        "selp.b32 %0, 1, 0, p;\n\t}"
        : "=r"(done) : "r"(a), "r"(parity) : "memory");
    if (!done) {
        asm volatile(
            "{\n\t.reg .pred P1;\n\t"
            "WL_%=:\n\t"
            "mbarrier.try_wait.parity.acquire.cta.shared::cta.b64 P1, [%0], %1, 0x989680;\n\t"
            "@P1 bra.uni WD_%=;\n\t"
            "bra.uni WL_%=;\n\t"
            "WD_%=:\n\t}"
            :: "r"(a), "r"(parity) : "memory");
    }
}

__device__ __forceinline__ void tma2d(uint32_t smem_addr, const void* tmap,
                                      int cx, int cy, uint32_t mbar) {
    asm volatile(
        "cp.async.bulk.tensor.2d.shared::cta.global.tile.mbarrier::complete_tx::bytes "
        "[%0], [%1, {%2, %3}], [%4];"
        :: "r"(smem_addr), "l"(tmap), "r"(cx), "r"(cy), "r"(mbar) : "memory");
}
#endif  // TCGEN05_OK

__global__ void __launch_bounds__(TC_THREADS, 1)
patch_mix_tc(const __grid_constant__ CUtensorMap tmA,
             const __grid_constant__ CUtensorMap tmB,
             float* __restrict__ y)
{
#if TCGEN05_OK
    extern __shared__ char smem[];
    const uint32_t smem_base = smem_u32(smem);
    const int tid  = threadIdx.x;
    const int warp = tid >> 5;
    const int lane = tid & 31;
    const int bN   = blockIdx.x;   // 0..3
    const int bM   = blockIdx.y;   // 0..255

    // ctrl: [0] tmem ptr; mbarriers: full[s]=64+16s, empty[s]=72+16s, done=160
    const uint32_t mb_full0  = smem_base + 64;
    const uint32_t mb_empty0 = smem_base + 72;
    const uint32_t mb_done   = smem_base + 160;

    if (warp == 0) {
        asm volatile("tcgen05.alloc.cta_group::1.sync.aligned.shared::cta.b32 [%0], %1;"
                     :: "r"(smem_base), "r"(512u) : "memory");
    }
    if (tid == 0) {
#pragma unroll
        for (int s = 0; s < TC_STAGES; ++s) {
            mbar_init(mb_full0 + 16 * s, 1);
            mbar_init(mb_empty0 + 16 * s, 1);
        }
        mbar_init(mb_done, 1);
    }
    __syncthreads();
    uint32_t tmem;
    asm volatile("ld.shared.b32 %0, [%1];" : "=r"(tmem) : "r"(smem_base));

    uint32_t Aaddr[TC_STAGES], Baddr[TC_STAGES];
#pragma unroll
    for (int s = 0; s < TC_STAGES; ++s) {
        Aaddr[s] = smem_base + TC_SMEM_CTRL + s * TC_STAGE_BYTES;
        Baddr[s] = Aaddr[s] + TC_A_BYTES;
    }

    if (warp == 0 && lane == 0) {
        // -------- producer: TMA, runs up to 3 tiles ahead
        for (int kt = 0; kt < TC_NKT; ++kt) {
            const int s = kt % TC_STAGES;
            if (kt >= TC_STAGES)
                mbar_wait(mb_empty0 + 16 * s, ((kt / TC_STAGES) - 1) & 1);
            const uint32_t full = mb_full0 + 16 * s;
            asm volatile("mbarrier.arrive.expect_tx.shared.b64 _, [%0], %1;"
                         :: "r"(full), "r"((uint32_t)TC_STAGE_BYTES) : "memory");
            tma2d(Aaddr[s], (const void*)&tmA, kt * 32, bM * TC_TILE_M, full);
            tma2d(Baddr[s], (const void*)&tmB, kt * 32, bN * TC_TILE_N, full);
        }
    }
    if (warp == 1 && lane == 0) {
        // -------- consumer: MMA issue + commits
        for (int kt = 0; kt < TC_NKT; ++kt) {
            const int s = kt % TC_STAGES;
            mbar_wait(mb_full0 + 16 * s, (kt / TC_STAGES) & 1);
            const uint64_t aD = make_desc(Aaddr[s]);
            const uint64_t bD = make_desc(Baddr[s]);
#pragma unroll
            for (int h = 0; h < 2; ++h) {
#pragma unroll
                for (int ks = 0; ks < 4; ++ks) {
                    mma_tf32_ss(tmem + h * 256,
                                aD + h * 1024 + ks * 2,   // +128 rows = +1024 units
                                bD + ks * 2,
                                (kt > 0 || ks > 0) ? 1u : 0u);
                }
            }
            asm volatile(
                "tcgen05.commit.cta_group::1.mbarrier::arrive::one.shared::cluster.b64 [%0];"
                :: "r"(mb_empty0 + 16 * s) : "memory");
            if (kt == TC_NKT - 1) {
                asm volatile(
                    "tcgen05.commit.cta_group::1.mbarrier::arrive::one.shared::cluster.b64 [%0];"
                    :: "r"(mb_done) : "memory");
            }
        }
    }

    // -------- all threads: wait for final MMA completion
    mbar_wait(mb_done, 0);
    asm volatile("tcgen05.fence::after_thread_sync;" ::: "memory");

    // -------- epilogue: 8 warps. h = M-half (warp>>2), p = lane partition (warp&3)
    {
        const int p = warp & 3;
        const int h = warp >> 2;
        const uint32_t tm = tmem + h * 256;
        const int mo = bM * TC_TILE_M + h * 128 + p * 32 + lane;
        const int ob  = mo >> 12;
        const int ohp = (mo >> 6) & 63;
        const int owp = mo & 63;
        float* yb = y + (((size_t)ob) << 22) + (ohp << 10) + owp * 4;

#pragma unroll
        for (int q = 0; q < 8; ++q) {
            uint32_t d[32];
            asm volatile(
                "tcgen05.ld.sync.aligned.32x32b.x32.b32 "
                "{%0,%1,%2,%3,%4,%5,%6,%7,%8,%9,%10,%11,%12,%13,%14,%15,"
                "%16,%17,%18,%19,%20,%21,%22,%23,%24,%25,%26,%27,%28,%29,%30,%31}, [%32];"
                : "=r"(d[0]), "=r"(d[1]), "=r"(d[2]), "=r"(d[3]), "=r"(d[4]), "=r"(d[5]),
                  "=r"(d[6]), "=r"(d[7]), "=r"(d[8]), "=r"(d[9]), "=r"(d[10]), "=r"(d[11]),
                  "=r"(d[12]), "=r"(d[13]), "=r"(d[14]), "=r"(d[15]), "=r"(d[16]), "=r"(d[17]),
                  "=r"(d[18]), "=r"(d[19]), "=r"(d[20]), "=r"(d[21]), "=r"(d[22]), "=r"(d[23]),
                  "=r"(d[24]), "=r"(d[25]), "=r"(d[26]), "=r"(d[27]), "=r"(d[28]), "=r"(d[29]),
                  "=r"(d[30]), "=r"(d[31])
                : "r"(tm + q * 32));
            asm volatile("tcgen05.wait::ld.sync.aligned;" ::: "memory");

            const int ebase = bN * TC_TILE_N + q * 32;
#pragma unroll
            for (int c4 = 0; c4 < 2; ++c4) {
                const int ce = (ebase >> 4) + c4;
#pragma unroll
                for (int ph = 0; ph < 4; ++ph) {
                    float4 o;
                    o.x = __uint_as_float(d[c4 * 16 + ph * 4 + 0]);
                    o.y = __uint_as_float(d[c4 * 16 + ph * 4 + 1]);
                    o.z = __uint_as_float(d[c4 * 16 + ph * 4 + 2]);
                    o.w = __uint_as_float(d[c4 * 16 + ph * 4 + 3]);
                    *(float4*)(yb + (((size_t)ce) << 16) + (ph << 8)) = o;
                }
            }
        }
    }

    asm volatile("tcgen05.fence::before_thread_sync;" ::: "memory");
    __syncthreads();
    if (warp == 0) {
        asm volatile("tcgen05.relinquish_alloc_permit.cta_group::1.sync.aligned;");
        asm volatile("tcgen05.dealloc.cta_group::1.sync.aligned.b32 %0, %1;"
                     :: "r"(tmem), "r"(512u));
    }
#else
    (void)tmA; (void)tmB; (void)y;
#endif
}

// ======================== fallback: proven R1 warp-mma ======================

#define FB_THREADS 256
#define FB_PADK    36
#define FB_ABUF    (128 * FB_PADK)
#define FB_SMEM_BYTES (4 * FB_ABUF * 4)

__device__ __forceinline__ void fb_mma(float d[4], const uint32_t a[4], const uint32_t b[2]) {
    asm volatile(
        "mma.sync.aligned.m16n8k8.row.col.f32.tf32.tf32.f32 "
        "{%0,%1,%2,%3}, {%4,%5,%6,%7}, {%8,%9}, {%0,%1,%2,%3};\n"
        : "+f"(d[0]), "+f"(d[1]), "+f"(d[2]), "+f"(d[3])
        : "r"(a[0]), "r"(a[1]), "r"(a[2]), "r"(a[3]),
          "r"(b[0]), "r"(b[1]));
}

__global__ void __launch_bounds__(FB_THREADS)
patch_mix_fb(const float* __restrict__ x,
             const float* __restrict__ Wm,
             float*       __restrict__ y)
{
    extern __shared__ float smemf[];
    float* As = smemf;
    float* Bs = smemf + 2 * FB_ABUF;

    const int tid  = threadIdx.x;
    const int bN   = blockIdx.x;
    const int bM   = blockIdx.y;

    const int lane = tid & 31;
    const int warp = tid >> 5;
    const int gid  = lane >> 2;
    const int tig  = lane & 3;
    const int wMo  = (warp >> 2) * 64;
    const int wNo  = (warp & 3) * 32;

    const int mA   = tid & 127;
    const int hsel = tid >> 7;

    const int m_g = bM * 128 + mA;
    const int bb  = m_g >> 12;
    const int hp  = (m_g >> 6) & 63;
    const int wp  = m_g & 63;

    const float* pA[4];
    const float* pB[4];
    int sAB[4];
#pragma unroll
    for (int l = 0; l < 4; ++l) {
        int k4   = 2 * l + hsel;
        int coff = k4 >> 2;
        int ph   = k4 & 3;
        pA[l] = x + (((size_t)(bb * 64 + coff)) << 16) + ((hp * 4 + ph) << 8) + wp * 4;
        pB[l] = Wm + (size_t)(bN * 128 + mA) * 1024 + k4 * 4;
        sAB[l] = mA * FB_PADK + k4 * 4;
    }

    float4 av[4], bv[4];
    float acc[4][4][4];
#pragma unroll
    for (int i = 0; i < 4; ++i)
#pragma unroll
        for (int j = 0; j < 4; ++j)
#pragma unroll
            for (int rr = 0; rr < 4; ++rr) acc[i][j][rr] = 0.0f;

#pragma unroll
    for (int l = 0; l < 4; ++l) {
        av[l] = *(const float4*)(pA[l]);
        bv[l] = *(const float4*)(pB[l]);
    }
#pragma unroll
    for (int l = 0; l < 4; ++l) {
        *(float4*)(As + sAB[l]) = cvt4(av[l]);
        *(float4*)(Bs + sAB[l]) = cvt4(bv[l]);
    }
    __syncthreads();

    for (int kt = 0; kt < 32; ++kt) {
        const int cur = kt & 1;
        if (kt < 31) {
#pragma unroll
            for (int l = 0; l < 4; ++l) {
                av[l] = *(const float4*)(pA[l] + (size_t)(kt + 1) * 131072);
                bv[l] = *(const float4*)(pB[l] + (kt + 1) * 32);
            }
        }
        const float* Ab = As + cur * FB_ABUF;
        const float* Bb = Bs + cur * FB_ABUF;
#pragma unroll
        for (int ks = 0; ks < 4; ++ks) {
            uint32_t af[4][4], bf[4][2];
            const int kc = ks * 8 + tig;
#pragma unroll
            for (int mt = 0; mt < 4; ++mt) {
                int rr = wMo + mt * 16 + gid;
                af[mt][0] = __float_as_uint(Ab[rr * FB_PADK + kc]);
                af[mt][1] = __float_as_uint(Ab[(rr + 8) * FB_PADK + kc]);
                af[mt][2] = __float_as_uint(Ab[rr * FB_PADK + kc + 4]);
                af[mt][3] = __float_as_uint(Ab[(rr + 8) * FB_PADK + kc + 4]);
            }
#pragma unroll
            for (int nt = 0; nt < 4; ++nt) {
                int rn = wNo + nt * 8 + gid;
                bf[nt][0] = __float_as_uint(Bb[rn * FB_PADK + kc]);
                bf[nt][1] = __float_as_uint(Bb[rn * FB_PADK + kc + 4]);
            }
#pragma unroll
            for (int mt = 0; mt < 4; ++mt)
#pragma unroll
                for (int nt = 0; nt < 4; ++nt)
                    fb_mma(acc[mt][nt], af[mt], bf[nt]);
        }
        if (kt < 31) {
            const int nxt = cur ^ 1;
#pragma unroll
            for (int l = 0; l < 4; ++l) {
                *(float4*)(As + nxt * FB_ABUF + sAB[l]) = cvt4(av[l]);
                *(float4*)(Bs + nxt * FB_ABUF + sAB[l]) = cvt4(bv[l]);
            }
            __syncthreads();
        }
    }

#pragma unroll
    for (int mt = 0; mt < 4; ++mt) {
#pragma unroll
        for (int h = 0; h < 2; ++h) {
            int m_out = bM * 128 + wMo + mt * 16 + gid + h * 8;
            int ob  = m_out >> 12;
            int ohp = (m_out >> 6) & 63;
            int owp = m_out & 63;
            float* ybase = y + (((size_t)ob) << 22) + (ohp << 10) + owp * 4;
#pragma unroll
            for (int nt = 0; nt < 4; ++nt) {
                int e   = bN * 128 + wNo + nt * 8 + 2 * tig;
                int ce  = e >> 4;
                int oph = (e >> 2) & 3;
                int opw = e & 3;
                float2 vv;
                vv.x = acc[mt][nt][h * 2];
                vv.y = acc[mt][nt][h * 2 + 1];
                *(float2*)(ybase + (ce << 16) + (oph << 8) + opw) = vv;
            }
        }
    }
}

// ======================== dispatch ==========================================

typedef CUresult (*EncodeTiledFn)(
    CUtensorMap*, CUtensorMapDataType, cuuint32_t, void*,
    const cuuint64_t*, const cuuint64_t*, const cuuint32_t*, const cuuint32_t*,
    CUtensorMapInterleave, CUtensorMapSwizzle, CUtensorMapL2promotion,
    CUtensorMapFloatOOBfill);

extern "C" void kernel_launch(void* const* d_in, const int* in_sizes, int n_in,
                              void* d_out, int out_size)
{
    const float* x  = (const float*)d_in[0];
    const float* Wm = (const float*)d_in[1];
    float*       y  = (float*)d_out;

    cudaFuncAttributes attr{};
    bool use_tc = false;
    if (cudaFuncGetAttributes(&attr, (const void*)patch_mix_tc) == cudaSuccess)
        use_tc = (attr.numRegs >= 40);

    EncodeTiledFn encode = nullptr;
    void* xr = nullptr;
    void* wr = nullptr;
    if (use_tc) {
        cudaDriverEntryPointQueryResult st;
        void* fn = nullptr;
        if (cudaGetDriverEntryPoint("cuTensorMapEncodeTiled", &fn,
                                    cudaEnableDefault, &st) == cudaSuccess &&
            st == cudaDriverEntryPointSuccess)
            encode = (EncodeTiledFn)fn;
        if (!encode ||
            cudaGetSymbolAddress(&xr, g_Xr) != cudaSuccess ||
            cudaGetSymbolAddress(&wr, g_Wr) != cudaSuccess)
            use_tc = false;
    }

    CUtensorMap tmA{}, tmB{};
    if (use_tc) {
        cuuint64_t dimsA[2]    = {1024, 65536};
        cuuint64_t strideA[1]  = {1024 * 4};
        cuuint32_t boxA[2]     = {32, 256};
        cuuint32_t es[2]       = {1, 1};
        cuuint64_t dimsB[2]    = {1024, 1024};
        cuuint64_t strideB[1]  = {1024 * 4};
        if (encode(&tmA, CU_TENSOR_MAP_DATA_TYPE_FLOAT32, 2, xr, dimsA, strideA,
                   boxA, es, CU_TENSOR_MAP_INTERLEAVE_NONE, CU_TENSOR_MAP_SWIZZLE_128B,
                   CU_TENSOR_MAP_L2_PROMOTION_L2_128B,
                   CU_TENSOR_MAP_FLOAT_OOB_FILL_NONE) != CUDA_SUCCESS)
            use_tc = false;
        else if (encode(&tmB, CU_TENSOR_MAP_DATA_TYPE_FLOAT32, 2, wr, dimsB, strideB,
                        boxA, es, CU_TENSOR_MAP_INTERLEAVE_NONE, CU_TENSOR_MAP_SWIZZLE_128B,
                        CU_TENSOR_MAP_L2_PROMOTION_L2_128B,
                        CU_TENSOR_MAP_FLOAT_OOB_FILL_NONE) != CUDA_SUCCESS)
            use_tc = false;
    }

    if (use_tc) {
        cudaFuncSetAttribute(pre_x, cudaFuncAttributeMaxDynamicSharedMemorySize, 32768);
        cudaFuncSetAttribute(patch_mix_tc,
                             cudaFuncAttributeMaxDynamicSharedMemorySize, TC_SMEM_BYTES);
        pre_x<<<8192, 256, 32768>>>(x);
        pre_w<<<1024, 256>>>(Wm);
        dim3 grid(4, 256);       // N inner: 4 CTAs per bM row share A tile in L2
        patch_mix_tc<<<grid, TC_THREADS, TC_SMEM_BYTES>>>(tmA, tmB, y);
    } else {
        cudaFuncSetAttribute(patch_mix_fb,
                             cudaFuncAttributeMaxDynamicSharedMemorySize, FB_SMEM_BYTES);
        dim3 grid(8, 512);
        patch_mix_fb<<<grid, FB_THREADS, FB_SMEM_BYTES>>>(x, Wm, y);
    }
}

// round 14
// speedup vs baseline: 1.3279x; 1.0729x over previous
#include <cuda_runtime.h>
#include <cuda.h>
#include <cstdint>

// ----------------------------------------------------------------------------
// BasePatchOrthogonalMix as one GEMM: out[m,e] = sum_d patch[m,d] * W[e,d]
//   m = (b,hp,wp) = 65536,  d/e = (c,ph,pw) = 1024
//
// R13:
//  * GEMM: unchanged from R12 (proven ~186 us single-CTA tcgen05 tf32,
//    256x256xK32, TMEM accum, 3-stage TMA ring; at the chip LTS cap).
//  * pre_x: load phase now cp.async.cg (LDGSTS) directly into XOR-swizzled
//    smem -> removes the LDG->RF->STS L1 double-pass, MLP=8 immediately.
//    Store phase (LDS + cvt.rna + STG) unchanged. pre_w merged into the same
//    launch (grid 8192 x-blocks + 64 W-blocks).
//  * cvt.rna.tf32 in pre-pass (tf32 truncation bias ~2^-10 > 1e-3 budget).
//  Fallback warp-mma kernel + numRegs dispatch retained.
// ----------------------------------------------------------------------------

#if defined(__CUDA_ARCH__) && (defined(__CUDA_ARCH_FEAT_SM103_ALL) || defined(__CUDA_ARCH_FEAT_SM100_ALL))
#define TCGEN05_OK 1
#else
#define TCGEN05_OK 0
#endif

// Scratch: A row-major [65536 x 1024], W row-major [1024 x 1024].
__device__ float g_Xr[65536ull * 1024];
__device__ float g_Wr[1024 * 1024];

// ======================== common helpers ====================================

__device__ __forceinline__ uint32_t f2tf32(float f) {
    uint32_t u;
    asm("cvt.rna.tf32.f32 %0, %1;" : "=r"(u) : "f"(f));
    return u;
}

__device__ __forceinline__ float4 cvt4(float4 v) {
    float4 t;
    t.x = __uint_as_float(f2tf32(v.x));
    t.y = __uint_as_float(f2tf32(v.y));
    t.z = __uint_as_float(f2tf32(v.z));
    t.w = __uint_as_float(f2tf32(v.w));
    return t;
}

__device__ __forceinline__ uint32_t smem_u32(const void* p) {
    uint32_t a;
    asm("{ .reg .u64 t; cvta.to.shared.u64 t, %1; cvt.u32.u64 %0, t; }" : "=r"(a) : "l"(p));
    return a;
}

// ======================== pre-pass kernel ===================================

// blocks [0, 8192): x transpose. CTA = (b, hp, cb8): 8 channels x 4 ph x 256 w
//   -> 64 m-rows x 128 d. smem 32 rows x 64 float4 (32 KB), XOR swizzle
//   col4' = col4 ^ (row & 7). Load phase via cp.async.cg (16 B each).
// blocks [8192, 8256): W rounding. 64 blocks x 256 thr x 16 float4.
__global__ void __launch_bounds__(256) pre_x(const float* __restrict__ x,
                                             const float* __restrict__ w) {
    extern __shared__ float4 sm[];   // 32 * 64 float4 = 32 KB
    const int t   = threadIdx.x;
    const int bid = blockIdx.x;

    if (bid >= 8192) {
        // ---- W rounding: 64 blocks cover 1M floats (262144 float4)
        const int base = ((bid - 8192) * 4096 + t) /*float4 idx*/;
#pragma unroll
        for (int k = 0; k < 16; ++k) {
            const int i = (base + k * 256) * 4;
            *(float4*)(g_Wr + i) = cvt4(*(const float4*)(w + i));
        }
        return;
    }

    const int cb8 = bid & 7;          // 8-channel block
    const int hp  = (bid >> 3) & 63;
    const int b   = bid >> 9;
    const uint32_t smb = smem_u32(sm);

    {   // load: row r = c2*4+ph (c2 0..7); 256 floats of x[b][cb8*8+c2][hp*4+ph][:]
        const int r = t >> 3, i = t & 7;
        const int c  = cb8 * 8 + (r >> 2);
        const int ph = r & 3;
        const float4* src = (const float4*)(x + (((size_t)(b * 64 + c)) << 16)
                                              + ((hp * 4 + ph) << 8));
#pragma unroll
        for (int jj = 0; jj < 8; ++jj) {
            int f = jj * 8 + i;
            uint32_t dst = smb + (uint32_t)(r * 64 + (f ^ (r & 7))) * 16u;
            asm volatile("cp.async.cg.shared.global [%0], [%1], 16;"
                         :: "r"(dst), "l"(src + f) : "memory");
        }
        asm volatile("cp.async.commit_group;" ::: "memory");
        asm volatile("cp.async.wait_group 0;" ::: "memory");
    }
    __syncthreads();
    {   // store: m-row (wp), 128 contiguous d at offset cb8*128, rna-rounded
        const int wp = t >> 2, i2 = t & 3;
        const int m  = b * 4096 + hp * 64 + wp;
        float4* dst = (float4*)(g_Xr + (size_t)m * 1024 + cb8 * 128);
#pragma unroll
        for (int jj = 0; jj < 8; ++jj) {
            int g = jj * 4 + i2;             // chunk g = c2*4+ph = smem row
            dst[g] = cvt4(sm[g * 64 + (wp ^ (g & 7))]);
        }
    }
}

// ======================== tcgen05 GEMM (R6 design) ==========================

#define TC_THREADS     256
#define TC_TILE_M      256
#define TC_TILE_N      256
#define TC_NKT         32
#define TC_STAGES      3
#define TC_A_BYTES     (TC_TILE_M * 128)
#define TC_B_BYTES     (TC_TILE_N * 128)
#define TC_STAGE_BYTES (TC_A_BYTES + TC_B_BYTES)          // 65536
#define TC_SMEM_CTRL   1024
#define TC_SMEM_BYTES  (TC_SMEM_CTRL + TC_STAGES * TC_STAGE_BYTES)   // 197632

// idesc kind::tf32: dtype=F32(1)<<4, atype=TF32(2)<<7, btype=TF32(2)<<10,
// n_dim=N>>3 at [17:23), m_dim=M>>4 at [24:29) (M=128 per MMA)
#define TC_IDESC  ((1u << 4) | (2u << 7) | (2u << 10) | ((TC_TILE_N / 8) << 17) | ((128 / 16) << 24))
// K-major SW128 desc base: layout=2<<61, version=1<<46, SBO=64<<32, LBO=1<<16
#define TC_DESC_BASE ((2ull << 61) | (1ull << 46) | (64ull << 32) | (1ull << 16))

#if TCGEN05_OK
__device__ __forceinline__ uint64_t make_desc(uint32_t addr) {
    return TC_DESC_BASE | ((uint64_t)(addr >> 4) & 0x3FFF);
}

__device__ __forceinline__ void mma_tf32_ss(uint32_t d_tmem, uint64_t ad, uint64_t bd,
                                            uint32_t en) {
    asm volatile(
        "{\n\t.reg .pred p;\n\tsetp.ne.u32 p, %4, 0;\n\t"
        "tcgen05.mma.cta_group::1.kind::tf32 [%0], %1, %2, %3, p;\n\t}"
        :: "r"(d_tmem), "l"(ad), "l"(bd), "r"(TC_IDESC), "r"(en) : "memory");
}

__device__ __forceinline__ void mbar_init(uint32_t a, uint32_t cnt) {
    asm volatile("mbarrier.init.shared.b64 [%0], %1;" :: "r"(a), "r"(cnt) : "memory");
}

__device__ __forceinline__ void mbar_wait(uint32_t a, uint32_t parity) {
    uint32_t done;
    asm volatile(
        "{\n\t.reg .pred p;\n\t"
        "mbarrier.try_wait.parity.acquire.cta.shared::cta.b64 p, [%1], %2;\n\t"
        "selp.b32 %0, 1, 0, p;\n\t}"
        : "=r"(done) : "r"(a), "r"(parity) : "memory");
    if (!done) {
        asm volatile(
            "{\n\t.reg .pred P1;\n\t"
            "WL_%=:\n\t"
            "mbarrier.try_wait.parity.acquire.cta.shared::cta.b64 P1, [%0], %1, 0x989680;\n\t"
            "@P1 bra.uni WD_%=;\n\t"
            "bra.uni WL_%=;\n\t"
            "WD_%=:\n\t}"
            :: "r"(a), "r"(parity) : "memory");
    }
}

__device__ __forceinline__ void tma2d(uint32_t smem_addr, const void* tmap,
                                      int cx, int cy, uint32_t mbar) {
    asm volatile(
        "cp.async.bulk.tensor.2d.shared::cta.global.tile.mbarrier::complete_tx::bytes "
        "[%0], [%1, {%2, %3}], [%4];"
        :: "r"(smem_addr), "l"(tmap), "r"(cx), "r"(cy), "r"(mbar) : "memory");
}
#endif  // TCGEN05_OK

__global__ void __launch_bounds__(TC_THREADS, 1)
patch_mix_tc(const __grid_constant__ CUtensorMap tmA,
             const __grid_constant__ CUtensorMap tmB,
             float* __restrict__ y)
{
#if TCGEN05_OK
    extern __shared__ char smem[];
    const uint32_t smem_base = smem_u32(smem);
    const int tid  = threadIdx.x;
    const int warp = tid >> 5;
    const int lane = tid & 31;
    const int bN   = blockIdx.x;   // 0..3
    const int bM   = blockIdx.y;   // 0..255

    // ctrl: [0] tmem ptr; mbarriers: full[s]=64+16s, empty[s]=72+16s, done=160
    const uint32_t mb_full0  = smem_base + 64;
    const uint32_t mb_empty0 = smem_base + 72;
    const uint32_t mb_done   = smem_base + 160;

    if (warp == 0) {
        asm volatile("tcgen05.alloc.cta_group::1.sync.aligned.shared::cta.b32 [%0], %1;"
                     :: "r"(smem_base), "r"(512u) : "memory");
    }
    if (tid == 0) {
#pragma unroll
        for (int s = 0; s < TC_STAGES; ++s) {
            mbar_init(mb_full0 + 16 * s, 1);
            mbar_init(mb_empty0 + 16 * s, 1);
        }
        mbar_init(mb_done, 1);
    }
    __syncthreads();
    uint32_t tmem;
    asm volatile("ld.shared.b32 %0, [%1];" : "=r"(tmem) : "r"(smem_base));

    uint32_t Aaddr[TC_STAGES], Baddr[TC_STAGES];
#pragma unroll
    for (int s = 0; s < TC_STAGES; ++s) {
        Aaddr[s] = smem_base + TC_SMEM_CTRL + s * TC_STAGE_BYTES;
        Baddr[s] = Aaddr[s] + TC_A_BYTES;
    }

    if (warp == 0 && lane == 0) {
        // -------- producer: TMA, runs up to 3 tiles ahead
        for (int kt = 0; kt < TC_NKT; ++kt) {
            const int s = kt % TC_STAGES;
            if (kt >= TC_STAGES)
                mbar_wait(mb_empty0 + 16 * s, ((kt / TC_STAGES) - 1) & 1);
            const uint32_t full = mb_full0 + 16 * s;
            asm volatile("mbarrier.arrive.expect_tx.shared.b64 _, [%0], %1;"
                         :: "r"(full), "r"((uint32_t)TC_STAGE_BYTES) : "memory");
            tma2d(Aaddr[s], (const void*)&tmA, kt * 32, bM * TC_TILE_M, full);
            tma2d(Baddr[s], (const void*)&tmB, kt * 32, bN * TC_TILE_N, full);
        }
    }
    if (warp == 1 && lane == 0) {
        // -------- consumer: MMA issue + commits
        for (int kt = 0; kt < TC_NKT; ++kt) {
            const int s = kt % TC_STAGES;
            mbar_wait(mb_full0 + 16 * s, (kt / TC_STAGES) & 1);
            const uint64_t aD = make_desc(Aaddr[s]);
            const uint64_t bD = make_desc(Baddr[s]);
#pragma unroll
            for (int h = 0; h < 2; ++h) {
#pragma unroll
                for (int ks = 0; ks < 4; ++ks) {
                    mma_tf32_ss(tmem + h * 256,
                                aD + h * 1024 + ks * 2,   // +128 rows = +1024 units
                                bD + ks * 2,
                                (kt > 0 || ks > 0) ? 1u : 0u);
                }
            }
            asm volatile(
                "tcgen05.commit.cta_group::1.mbarrier::arrive::one.shared::cluster.b64 [%0];"
                :: "r"(mb_empty0 + 16 * s) : "memory");
            if (kt == TC_NKT - 1) {
                asm volatile(
                    "tcgen05.commit.cta_group::1.mbarrier::arrive::one.shared::cluster.b64 [%0];"
                    :: "r"(mb_done) : "memory");
            }
        }
    }

    // -------- all threads: wait for final MMA completion
    mbar_wait(mb_done, 0);
    asm volatile("tcgen05.fence::after_thread_sync;" ::: "memory");

    // -------- epilogue: 8 warps. h = M-half (warp>>2), p = lane partition (warp&3)
    {
        const int p = warp & 3;
        const int h = warp >> 2;
        const uint32_t tm = tmem + h * 256;
        const int mo = bM * TC_TILE_M + h * 128 + p * 32 + lane;
        const int ob  = mo >> 12;
        const int ohp = (mo >> 6) & 63;
        const int owp = mo & 63;
        float* yb = y + (((size_t)ob) << 22) + (ohp << 10) + owp * 4;

#pragma unroll
        for (int q = 0; q < 8; ++q) {
            uint32_t d[32];
            asm volatile(
                "tcgen05.ld.sync.aligned.32x32b.x32.b32 "
                "{%0,%1,%2,%3,%4,%5,%6,%7,%8,%9,%10,%11,%12,%13,%14,%15,"
                "%16,%17,%18,%19,%20,%21,%22,%23,%24,%25,%26,%27,%28,%29,%30,%31}, [%32];"
                : "=r"(d[0]), "=r"(d[1]), "=r"(d[2]), "=r"(d[3]), "=r"(d[4]), "=r"(d[5]),
                  "=r"(d[6]), "=r"(d[7]), "=r"(d[8]), "=r"(d[9]), "=r"(d[10]), "=r"(d[11]),
                  "=r"(d[12]), "=r"(d[13]), "=r"(d[14]), "=r"(d[15]), "=r"(d[16]), "=r"(d[17]),
                  "=r"(d[18]), "=r"(d[19]), "=r"(d[20]), "=r"(d[21]), "=r"(d[22]), "=r"(d[23]),
                  "=r"(d[24]), "=r"(d[25]), "=r"(d[26]), "=r"(d[27]), "=r"(d[28]), "=r"(d[29]),
                  "=r"(d[30]), "=r"(d[31])
                : "r"(tm + q * 32));
            asm volatile("tcgen05.wait::ld.sync.aligned;" ::: "memory");

            const int ebase = bN * TC_TILE_N + q * 32;
#pragma unroll
            for (int c4 = 0; c4 < 2; ++c4) {
                const int ce = (ebase >> 4) + c4;
#pragma unroll
                for (int ph = 0; ph < 4; ++ph) {
                    float4 o;
                    o.x = __uint_as_float(d[c4 * 16 + ph * 4 + 0]);
                    o.y = __uint_as_float(d[c4 * 16 + ph * 4 + 1]);
                    o.z = __uint_as_float(d[c4 * 16 + ph * 4 + 2]);
                    o.w = __uint_as_float(d[c4 * 16 + ph * 4 + 3]);
                    *(float4*)(yb + (((size_t)ce) << 16) + (ph << 8)) = o;
                }
            }
        }
    }

    asm volatile("tcgen05.fence::before_thread_sync;" ::: "memory");
    __syncthreads();
    if (warp == 0) {
        asm volatile("tcgen05.relinquish_alloc_permit.cta_group::1.sync.aligned;");
        asm volatile("tcgen05.dealloc.cta_group::1.sync.aligned.b32 %0, %1;"
                     :: "r"(tmem), "r"(512u));
    }
#else
    (void)tmA; (void)tmB; (void)y;
#endif
}

// ======================== fallback: proven R1 warp-mma ======================

#define FB_THREADS 256
#define FB_PADK    36
#define FB_ABUF    (128 * FB_PADK)
#define FB_SMEM_BYTES (4 * FB_ABUF * 4)

__device__ __forceinline__ void fb_mma(float d[4], const uint32_t a[4], const uint32_t b[2]) {
    asm volatile(
        "mma.sync.aligned.m16n8k8.row.col.f32.tf32.tf32.f32 "
        "{%0,%1,%2,%3}, {%4,%5,%6,%7}, {%8,%9}, {%0,%1,%2,%3};\n"
        : "+f"(d[0]), "+f"(d[1]), "+f"(d[2]), "+f"(d[3])
        : "r"(a[0]), "r"(a[1]), "r"(a[2]), "r"(a[3]),
          "r"(b[0]), "r"(b[1]));
}

__global__ void __launch_bounds__(FB_THREADS)
patch_mix_fb(const float* __restrict__ x,
             const float* __restrict__ Wm,
             float*       __restrict__ y)
{
    extern __shared__ float smemf[];
    float* As = smemf;
    float* Bs = smemf + 2 * FB_ABUF;

    const int tid  = threadIdx.x;
    const int bN   = blockIdx.x;
    const int bM   = blockIdx.y;

    const int lane = tid & 31;
    const int warp = tid >> 5;
    const int gid  = lane >> 2;
    const int tig  = lane & 3;
    const int wMo  = (warp >> 2) * 64;
    const int wNo  = (warp & 3) * 32;

    const int mA   = tid & 127;
    const int hsel = tid >> 7;

    const int m_g = bM * 128 + mA;
    const int bb  = m_g >> 12;
    const int hp  = (m_g >> 6) & 63;
    const int wp  = m_g & 63;

    const float* pA[4];
    const float* pB[4];
    int sAB[4];
#pragma unroll
    for (int l = 0; l < 4; ++l) {
        int k4   = 2 * l + hsel;
        int coff = k4 >> 2;
        int ph   = k4 & 3;
        pA[l] = x + (((size_t)(bb * 64 + coff)) << 16) + ((hp * 4 + ph) << 8) + wp * 4;
        pB[l] = Wm + (size_t)(bN * 128 + mA) * 1024 + k4 * 4;
        sAB[l] = mA * FB_PADK + k4 * 4;
    }

    float4 av[4], bv[4];
    float acc[4][4][4];
#pragma unroll
    for (int i = 0; i < 4; ++i)
#pragma unroll
        for (int j = 0; j < 4; ++j)
#pragma unroll
            for (int rr = 0; rr < 4; ++rr) acc[i][j][rr] = 0.0f;

#pragma unroll
    for (int l = 0; l < 4; ++l) {
        av[l] = *(const float4*)(pA[l]);
        bv[l] = *(const float4*)(pB[l]);
    }
#pragma unroll
    for (int l = 0; l < 4; ++l) {
        *(float4*)(As + sAB[l]) = cvt4(av[l]);
        *(float4*)(Bs + sAB[l]) = cvt4(bv[l]);
    }
    __syncthreads();

    for (int kt = 0; kt < 32; ++kt) {
        const int cur = kt & 1;
        if (kt < 31) {
#pragma unroll
            for (int l = 0; l < 4; ++l) {
                av[l] = *(const float4*)(pA[l] + (size_t)(kt + 1) * 131072);
                bv[l] = *(const float4*)(pB[l] + (kt + 1) * 32);
            }
        }
        const float* Ab = As + cur * FB_ABUF;
        const float* Bb = Bs + cur * FB_ABUF;
#pragma unroll
        for (int ks = 0; ks < 4; ++ks) {
            uint32_t af[4][4], bf[4][2];
            const int kc = ks * 8 + tig;
#pragma unroll
            for (int mt = 0; mt < 4; ++mt) {
                int rr = wMo + mt * 16 + gid;
                af[mt][0] = __float_as_uint(Ab[rr * FB_PADK + kc]);
                af[mt][1] = __float_as_uint(Ab[(rr + 8) * FB_PADK + kc]);
                af[mt][2] = __float_as_uint(Ab[rr * FB_PADK + kc + 4]);
                af[mt][3] = __float_as_uint(Ab[(rr + 8) * FB_PADK + kc + 4]);
            }
#pragma unroll
            for (int nt = 0; nt < 4; ++nt) {
                int rn = wNo + nt * 8 + gid;
                bf[nt][0] = __float_as_uint(Bb[rn * FB_PADK + kc]);
                bf[nt][1] = __float_as_uint(Bb[rn * FB_PADK + kc + 4]);
            }
#pragma unroll
            for (int mt = 0; mt < 4; ++mt)
#pragma unroll
                for (int nt = 0; nt < 4; ++nt)
                    fb_mma(acc[mt][nt], af[mt], bf[nt]);
        }
        if (kt < 31) {
            const int nxt = cur ^ 1;
#pragma unroll
            for (int l = 0; l < 4; ++l) {
                *(float4*)(As + nxt * FB_ABUF + sAB[l]) = cvt4(av[l]);
                *(float4*)(Bs + nxt * FB_ABUF + sAB[l]) = cvt4(bv[l]);
            }
            __syncthreads();
        }
    }

#pragma unroll
    for (int mt = 0; mt < 4; ++mt) {
#pragma unroll
        for (int h = 0; h < 2; ++h) {
            int m_out = bM * 128 + wMo + mt * 16 + gid + h * 8;
            int ob  = m_out >> 12;
            int ohp = (m_out >> 6) & 63;
            int owp = m_out & 63;
            float* ybase = y + (((size_t)ob) << 22) + (ohp << 10) + owp * 4;
#pragma unroll
            for (int nt = 0; nt < 4; ++nt) {
                int e   = bN * 128 + wNo + nt * 8 + 2 * tig;
                int ce  = e >> 4;
                int oph = (e >> 2) & 3;
                int opw = e & 3;
                float2 vv;
                vv.x = acc[mt][nt][h * 2];
                vv.y = acc[mt][nt][h * 2 + 1];
                *(float2*)(ybase + (ce << 16) + (oph << 8) + opw) = vv;
            }
        }
    }
}

// ======================== dispatch ==========================================

typedef CUresult (*EncodeTiledFn)(
    CUtensorMap*, CUtensorMapDataType, cuuint32_t, void*,
    const cuuint64_t*, const cuuint64_t*, const cuuint32_t*, const cuuint32_t*,
    CUtensorMapInterleave, CUtensorMapSwizzle, CUtensorMapL2promotion,
    CUtensorMapFloatOOBfill);

extern "C" void kernel_launch(void* const* d_in, const int* in_sizes, int n_in,
                              void* d_out, int out_size)
{
    const float* x  = (const float*)d_in[0];
    const float* Wm = (const float*)d_in[1];
    float*       y  = (float*)d_out;

    cudaFuncAttributes attr{};
    bool use_tc = false;
    if (cudaFuncGetAttributes(&attr, (const void*)patch_mix_tc) == cudaSuccess)
        use_tc = (attr.numRegs >= 40);

    EncodeTiledFn encode = nullptr;
    void* xr = nullptr;
    void* wr = nullptr;
    if (use_tc) {
        cudaDriverEntryPointQueryResult st;
        void* fn = nullptr;
        if (cudaGetDriverEntryPoint("cuTensorMapEncodeTiled", &fn,
                                    cudaEnableDefault, &st) == cudaSuccess &&
            st == cudaDriverEntryPointSuccess)
            encode = (EncodeTiledFn)fn;
        if (!encode ||
            cudaGetSymbolAddress(&xr, g_Xr) != cudaSuccess ||
            cudaGetSymbolAddress(&wr, g_Wr) != cudaSuccess)
            use_tc = false;
    }

    CUtensorMap tmA{}, tmB{};
    if (use_tc) {
        cuuint64_t dimsA[2]    = {1024, 65536};
        cuuint64_t strideA[1]  = {1024 * 4};
        cuuint32_t boxA[2]     = {32, 256};
        cuuint32_t es[2]       = {1, 1};
        cuuint64_t dimsB[2]    = {1024, 1024};
        cuuint64_t strideB[1]  = {1024 * 4};
        if (encode(&tmA, CU_TENSOR_MAP_DATA_TYPE_FLOAT32, 2, xr, dimsA, strideA,
                   boxA, es, CU_TENSOR_MAP_INTERLEAVE_NONE, CU_TENSOR_MAP_SWIZZLE_128B,
                   CU_TENSOR_MAP_L2_PROMOTION_L2_128B,
                   CU_TENSOR_MAP_FLOAT_OOB_FILL_NONE) != CUDA_SUCCESS)
            use_tc = false;
        else if (encode(&tmB, CU_TENSOR_MAP_DATA_TYPE_FLOAT32, 2, wr, dimsB, strideB,
                        boxA, es, CU_TENSOR_MAP_INTERLEAVE_NONE, CU_TENSOR_MAP_SWIZZLE_128B,
                        CU_TENSOR_MAP_L2_PROMOTION_L2_128B,
                        CU_TENSOR_MAP_FLOAT_OOB_FILL_NONE) != CUDA_SUCCESS)
            use_tc = false;
    }

    if (use_tc) {
        cudaFuncSetAttribute(pre_x, cudaFuncAttributeMaxDynamicSharedMemorySize, 32768);
        cudaFuncSetAttribute(patch_mix_tc,
                             cudaFuncAttributeMaxDynamicSharedMemorySize, TC_SMEM_BYTES);
        pre_x<<<8256, 256, 32768>>>(x, Wm);   // 8192 x-blocks + 64 W-blocks
        dim3 grid(4, 256);       // N inner: 4 CTAs per bM row share A tile in L2
        patch_mix_tc<<<grid, TC_THREADS, TC_SMEM_BYTES>>>(tmA, tmB, y);
    } else {
        cudaFuncSetAttribute(patch_mix_fb,
                             cudaFuncAttributeMaxDynamicSharedMemorySize, FB_SMEM_BYTES);
        dim3 grid(8, 512);
        patch_mix_fb<<<grid, FB_THREADS, FB_SMEM_BYTES>>>(x, Wm, y);
    }
}